// round 4
// baseline (speedup 1.0000x reference)
#include <cuda_runtime.h>
#include <math.h>

#define BN 32
#define TIN 256
#define TOUT 400
#define EDIM 512
#define ADIM 128
#define NFLT 32
#define KSZ 31
#define PRE 256
#define DDIM 1024
#define NMEL 80
#define ZN 4096
#define NCTA 128
#define NTHR 256

// ---------------- persistent device scratch ----------------
__device__ float g_prenet[TOUT * BN * PRE];   // [t][b][k]
__device__ float g_keysT[BN * ADIM * TIN];    // [b][a][t]
__device__ float g_maskneg[BN * TIN];         // 0 or -1e9
__device__ float g_h0[2][BN * DDIM];
__device__ float g_h1[2][BN * DDIM];
__device__ float g_ctx[BN * EDIM];
__device__ float g_wcum[BN * TIN];
__device__ float g_epart[4 * BN * TIN];       // [achunk][b][ti]
__device__ float g_h1all[TOUT * BN * DDIM];   // [t][b][d]
__device__ float g_ctxall[TOUT * BN * EDIM];  // [t][b][e]
__device__ unsigned g_barc;
__device__ volatile unsigned g_barg;

// ---------------- f32x2 helpers ----------------
__device__ __forceinline__ unsigned long long dupf(float w) {
    unsigned long long r;
    asm("mov.b64 %0, {%1, %1};" : "=l"(r) : "f"(w));
    return r;
}
__device__ __forceinline__ void fma2(unsigned long long& acc, unsigned long long x,
                                     unsigned long long w) {
    asm("fma.rn.f32x2 %0, %1, %2, %0;" : "+l"(acc) : "l"(x), "l"(w));
}
__device__ __forceinline__ unsigned long long add2(unsigned long long a,
                                                   unsigned long long b) {
    unsigned long long r;
    asm("add.rn.f32x2 %0, %1, %2;" : "=l"(r) : "l"(a), "l"(b));
    return r;
}
__device__ __forceinline__ void unpack2(float& lo, float& hi, unsigned long long v) {
    asm("mov.b64 {%0, %1}, %2;" : "=f"(lo), "=f"(hi) : "l"(v));
}
__device__ __forceinline__ float sigmoidf_(float x) { return 1.f / (1.f + expf(-x)); }

// ---------------- shared memory union ----------------
struct SmemGemm { float xs[4][32][33]; };
struct SmemRed  { unsigned long long sred[4][64][8]; float zf[32][32]; };
struct SmemAttC {
    float wp[TIN + KSZ];
    float cws[KSZ * NFLT];
    float cbs[NFLT];
    float ldws[NFLT * 32];
    float ldbs[32], vws[32];
    float qred[8][32];
    float qp[32];
};
struct SmemAttD { float red[256]; float ws[256]; float cred[2][128]; };
union SmemU { SmemGemm g; SmemRed r; SmemAttC c; SmemAttD d; };

// ---------------- grid barrier (sense-reversal, all 128 CTAs resident) --------
__device__ __forceinline__ void grid_bar() {
    __syncthreads();
    if (threadIdx.x == 0) {
        __threadfence();
        unsigned gen = g_barg;
        if (atomicInc(&g_barc, NCTA - 1) == NCTA - 1) {
            g_barg = gen + 1;
            __threadfence();
        } else {
            while (g_barg == gen) __nanosleep(32);
        }
        __threadfence();   // acquire side
    }
    __syncthreads();
}

// ---------------- mask prologue: detect bool-vs-int32 storage, build maskneg --
__global__ void mask_kernel(const unsigned char* __restrict__ mask) {
    __shared__ int s_has;
    int tid = threadIdx.x;
    if (tid == 0) s_has = 0;
    __syncthreads();
    // scan first BN*TIN bytes (valid under BOTH interpretations)
    int local = 0;
    for (int i = tid; i < BN * TIN; i += 256)
        if ((i & 3) != 0 && mask[i] != 0) local = 1;
    if (local) atomicOr(&s_has, 1);
    __syncthreads();
    bool is_u8 = (s_has != 0);
    const int* mi = (const int*)mask;
    for (int i = tid; i < BN * TIN; i += 256) {
        int v = is_u8 ? (int)mask[i] : mi[i];
        g_maskneg[i] = v ? 0.f : -1e9f;
    }
}

// ---------------- GEMM: 32 rows x (32 cols owned by CTA) x KTOT, 4-way k-split
// columns of CTA j: {1024*g + 8*j + i : g<4, i<8}
// result (fp32, fully reduced) lands in sm.r.zf[row][g*8 + i]
template <int KTOT, int KB0, int KB1, int SA>
__device__ __forceinline__ void gemm_block(SmemU& sm, int jcta,
                                           const float* __restrict__ xA,
                                           const float* __restrict__ xB,
                                           const float* __restrict__ xC,
                                           const float* __restrict__ wK,
                                           const float* __restrict__ wR) {
    constexpr int KC = KTOT / 4;
    constexpr int NT = KC / 32;
    const int tid = threadIdx.x;
    const int ks = tid >> 6, rg = (tid >> 3) & 7, ch = tid & 7;
    const int g = ch >> 1, half = ch & 1;
    const int colbase = 1024 * g + 8 * jcta + 4 * half;

    unsigned long long acc[8];
    #pragma unroll
    for (int i = 0; i < 8; i++) acc[i] = 0ULL;

    for (int tile = 0; tile < NT; tile++) {
        __syncthreads();
        #pragma unroll
        for (int i = 0; i < 16; i++) {
            int idx = i * 256 + tid;
            int row = idx >> 7, kk = idx & 127;
            int kss = kk >> 5, kl = kk & 31;
            int kg = kss * KC + tile * 32 + kl;
            float v;
            if (kg < KB0)      v = __ldcg(xA + row * SA + kg);
            else if (kg < KB1) v = __ldcg(xB + row * EDIM + (kg - KB0));
            else               v = __ldcg(xC + row * DDIM + (kg - KB1));
            sm.g.xs[kss][kl][row] = v;
        }
        __syncthreads();
        const int kq = ks * KC + tile * 32;
        #pragma unroll 8
        for (int kl = 0; kl < 32; kl++) {
            int kg = kq + kl;
            const float* wrow = (kg < KB1) ? (wK + (size_t)kg * ZN)
                                           : (wR + (size_t)(kg - KB1) * ZN);
            ulonglong2 wv = *(const ulonglong2*)(wrow + colbase);
            const float* xr = &sm.g.xs[ks][kl][4 * rg];
            #pragma unroll
            for (int r = 0; r < 4; r++) {
                unsigned long long xd = dupf(xr[r]);
                fma2(acc[r],     xd, wv.x);
                fma2(acc[4 + r], xd, wv.y);
            }
        }
    }
    __syncthreads();
    #pragma unroll
    for (int i = 0; i < 8; i++) sm.r.sred[ks][rg * 8 + ch][i] = acc[i];
    __syncthreads();
    if (tid < 64) {
        #pragma unroll
        for (int i = 0; i < 8; i++) {
            unsigned long long s = sm.r.sred[0][tid][i];
            s = add2(s, sm.r.sred[1][tid][i]);
            s = add2(s, sm.r.sred[2][tid][i]);
            s = add2(s, sm.r.sred[3][tid][i]);
            int p = i >> 2, r = i & 3;
            int lc = g * 8 + 4 * half + 2 * p;
            float lo, hi;
            unpack2(lo, hi, s);
            sm.r.zf[4 * rg + r][lc]     = lo;
            sm.r.zf[4 * rg + r][lc + 1] = hi;
        }
    }
    __syncthreads();
}

// ---------------- persistent decoder kernel ----------------
__global__ __launch_bounds__(NTHR, 1) void decoder_persist(
    const float* __restrict__ memory,
    const float* __restrict__ l0k, const float* __restrict__ l0r,
    const float* __restrict__ l0b,
    const float* __restrict__ l1k, const float* __restrict__ l1r,
    const float* __restrict__ l1b,
    const float* __restrict__ qw, const float* __restrict__ qb,
    const float* __restrict__ vw, const float* __restrict__ vb,
    const float* __restrict__ cw, const float* __restrict__ cb,
    const float* __restrict__ ldw, const float* __restrict__ ldb,
    float* __restrict__ out_align) {
    __shared__ SmemU sm;
    const int j = blockIdx.x;
    const int tid = threadIdx.x;

    // ---- init state (each of 32768 threads owns one unit index) ----
    {
        int i = j * NTHR + tid;  // 0..32767
        g_h0[0][i] = 0.f; g_h0[1][i] = 0.f;
        g_h1[0][i] = 0.f; g_h1[1][i] = 0.f;
        if (i < BN * EDIM) g_ctx[i] = 0.f;
        if (i < BN * TIN)  g_wcum[i] = 0.f;
    }
    float c0r = 0.f, c1r = 0.f;   // cell state in registers for all 400 steps
    const int bq = tid >> 3, dd = tid & 7;     // act mapping: unit (bq, 8*j+dd)
    const int du = 8 * j + dd;
    const int ab = j >> 2, ach = j & 3;        // attention mapping

    grid_bar();

    for (int t = 0; t < TOUT; t++) {
        const int rb = t & 1, wb = (t + 1) & 1;

        // ======== phase A: LSTM0 GEMM + gates ========
        gemm_block<1792, 256, 768, PRE>(sm, j, g_prenet + (size_t)t * BN * PRE,
                                        g_ctx, g_h0[rb], l0k, l0r);
        {
            float zi = sm.r.zf[bq][dd]      + l0b[du];
            float zff = sm.r.zf[bq][8 + dd] + l0b[1024 + du];
            float zg = sm.r.zf[bq][16 + dd] + l0b[2048 + du];
            float zo = sm.r.zf[bq][24 + dd] + l0b[3072 + du];
            float ii = sigmoidf_(zi), ff = sigmoidf_(zff), oo = sigmoidf_(zo);
            c0r = ff * c0r + ii * tanhf(zg);
            __stcg(&g_h0[wb][bq * DDIM + du], oo * tanhf(c0r));
        }
        grid_bar();

        // ======== phase B: LSTM1 GEMM + gates ========
        gemm_block<2560, 1024, 1536, DDIM>(sm, j, g_h0[wb], g_ctx, g_h1[rb],
                                           l1k, l1r);
        {
            float zi = sm.r.zf[bq][dd]      + l1b[du];
            float zff = sm.r.zf[bq][8 + dd] + l1b[1024 + du];
            float zg = sm.r.zf[bq][16 + dd] + l1b[2048 + du];
            float zo = sm.r.zf[bq][24 + dd] + l1b[3072 + du];
            float ii = sigmoidf_(zi), ff = sigmoidf_(zff), oo = sigmoidf_(zo);
            c1r = ff * c1r + ii * tanhf(zg);
            float h = oo * tanhf(c1r);
            __stcg(&g_h1[wb][bq * DDIM + du], h);
            g_h1all[((size_t)t * BN + bq) * DDIM + du] = h;
        }
        grid_bar();

        // ======== phase C: attention energies (CTA = b x a-chunk) ========
        {
            const float* h1cur = g_h1[wb];
            {
                int al = tid & 31, part = tid >> 5;
                float a0 = 0.f;
                int k0 = part * 128;
                #pragma unroll 4
                for (int k = k0; k < k0 + 128; k++)
                    a0 += __ldcg(h1cur + ab * DDIM + k) * qw[k * ADIM + ach * 32 + al];
                sm.c.qred[part][al] = a0;
            }
            for (int i = tid; i < TIN + KSZ - 1; i += NTHR) {
                int jj = i - (KSZ / 2);
                sm.c.wp[i] = (jj >= 0 && jj < TIN) ? __ldcg(&g_wcum[ab * TIN + jj]) : 0.f;
            }
            for (int i = tid; i < KSZ * NFLT; i += NTHR) sm.c.cws[i] = cw[i];
            if (tid < NFLT) sm.c.cbs[tid] = cb[tid];
            for (int i = tid; i < NFLT * 32; i += NTHR) {
                int f = i >> 5, al = i & 31;
                sm.c.ldws[i] = ldw[f * ADIM + ach * 32 + al];
            }
            if (tid < 32) {
                sm.c.ldbs[tid] = ldb[ach * 32 + tid];
                sm.c.vws[tid]  = vw[ach * 32 + tid];
            }
            __syncthreads();
            if (tid < 32) {
                float s = 0.f;
                #pragma unroll
                for (int p = 0; p < 8; p++) s += sm.c.qred[p][tid];
                sm.c.qp[tid] = s + qb[ach * 32 + tid];
            }
            __syncthreads();
            {
                int ti = tid;
                float locf[NFLT];
                #pragma unroll
                for (int f = 0; f < NFLT; f++) locf[f] = sm.c.cbs[f];
                for (int jk = 0; jk < KSZ; jk++) {
                    float w = sm.c.wp[ti + jk];
                    #pragma unroll
                    for (int f = 0; f < NFLT; f++) locf[f] += w * sm.c.cws[jk * NFLT + f];
                }
                float e = 0.f;
                #pragma unroll 4
                for (int al = 0; al < 32; al++) {
                    int a = ach * 32 + al;
                    float s = sm.c.qp[al] + g_keysT[(ab * ADIM + a) * TIN + ti] +
                              sm.c.ldbs[al];
                    #pragma unroll
                    for (int f = 0; f < NFLT; f++) s += locf[f] * sm.c.ldws[f * 32 + al];
                    e += tanhf(s) * sm.c.vws[al];
                }
                __stcg(&g_epart[(ach * BN + ab) * TIN + ti], e);
            }
        }
        grid_bar();

        // ======== phase D: softmax + context (CTA = b x E-chunk) ========
        {
            const int ec = ach;
            int ti = tid;
            float ev = vb[0] + g_maskneg[ab * TIN + ti];
            #pragma unroll
            for (int ac = 0; ac < 4; ac++)
                ev += __ldcg(&g_epart[(ac * BN + ab) * TIN + ti]);
            sm.d.red[ti] = ev;
            __syncthreads();
            for (int s = 128; s > 0; s >>= 1) {
                if (tid < s) sm.d.red[tid] = fmaxf(sm.d.red[tid], sm.d.red[tid + s]);
                __syncthreads();
            }
            float mx = sm.d.red[0];
            __syncthreads();
            float ex = expf(ev - mx);
            sm.d.red[ti] = ex;
            __syncthreads();
            for (int s = 128; s > 0; s >>= 1) {
                if (tid < s) sm.d.red[tid] += sm.d.red[tid + s];
                __syncthreads();
            }
            float inv = 1.f / sm.d.red[0];
            __syncthreads();
            float w = ex * inv;
            sm.d.ws[ti] = w;
            if (ec == 0) {
                __stcg(&g_wcum[ab * TIN + ti], __ldcg(&g_wcum[ab * TIN + ti]) + w);
                out_align[((size_t)ab * TOUT + t) * TIN + ti] = w;
            }
            __syncthreads();
            {
                int c = ec * 128 + (tid & 127);
                int hv = tid >> 7;
                float acc = 0.f;
                #pragma unroll 4
                for (int tt = hv * 128; tt < hv * 128 + 128; tt++)
                    acc += sm.d.ws[tt] * memory[((size_t)ab * TIN + tt) * EDIM + c];
                sm.d.cred[hv][tid & 127] = acc;
                __syncthreads();
                if (tid < 128) {
                    float cv = sm.d.cred[0][tid] + sm.d.cred[1][tid];
                    __stcg(&g_ctx[ab * EDIM + ec * 128 + tid], cv);
                    g_ctxall[((size_t)t * BN + ab) * EDIM + ec * 128 + tid] = cv;
                }
            }
        }
        grid_bar();
    }
}

// ---------------- prenet (teacher-forced, fully parallel) ----------------
__global__ void prenet_kernel(const float* __restrict__ targets,
                              const float* __restrict__ w1, const float* __restrict__ b1,
                              const float* __restrict__ w2, const float* __restrict__ b2) {
    int bid = blockIdx.x;          // t*BN + b
    int t = bid >> 5, b = bid & 31;
    __shared__ float xin[NMEL];
    __shared__ float h[PRE];
    int tid = threadIdx.x;         // 256
    if (tid < NMEL) xin[tid] = (t == 0) ? 0.f : targets[(b * TOUT + (t - 1)) * NMEL + tid];
    __syncthreads();
    float acc = b1[tid];
    #pragma unroll 8
    for (int k = 0; k < NMEL; k++) acc += xin[k] * w1[k * PRE + tid];
    h[tid] = fmaxf(acc, 0.f);
    __syncthreads();
    float acc2 = b2[tid];
    #pragma unroll 8
    for (int k = 0; k < PRE; k++) acc2 += h[k] * w2[k * PRE + tid];
    g_prenet[(t * BN + b) * PRE + tid] = fmaxf(acc2, 0.f);
}

// ---------------- keys projection, stored transposed [b][a][t] ----------------
__global__ void keys_kernel(const float* __restrict__ memory,
                            const float* __restrict__ mw, const float* __restrict__ mb) {
    int bid = blockIdx.x;          // b*TIN + t
    int b = bid >> 8, t = bid & 255;
    __shared__ float x[EDIM];
    int tid = threadIdx.x;         // 128
    for (int i = tid; i < EDIM; i += 128) x[i] = memory[(b * TIN + t) * EDIM + i];
    __syncthreads();
    float acc = mb[tid];
    #pragma unroll 8
    for (int k = 0; k < EDIM; k++) acc += x[k] * mw[k * ADIM + tid];
    g_keysT[(b * ADIM + tid) * TIN + t] = acc;
}

// ---------------- output projections (post-pass) ----------------
__global__ void proj_kernel(const float* __restrict__ pw, const float* __restrict__ pb,
                            const float* __restrict__ gw, const float* __restrict__ gb,
                            float* __restrict__ out_mel, float* __restrict__ out_gate) {
    int bid = blockIdx.x;          // t*BN + b
    int t = bid >> 5, b = bid & 31;
    __shared__ float xo[DDIM + EDIM];
    int tid = threadIdx.x;         // 128
    for (int i = tid; i < DDIM; i += 128) xo[i] = g_h1all[(size_t)(t * BN + b) * DDIM + i];
    for (int i = tid; i < EDIM; i += 128) xo[DDIM + i] = g_ctxall[(size_t)(t * BN + b) * EDIM + i];
    __syncthreads();
    if (tid < NMEL) {
        float acc = pb[tid];
        #pragma unroll 8
        for (int k = 0; k < DDIM + EDIM; k++) acc += xo[k] * pw[k * NMEL + tid];
        out_mel[(size_t)(b * TOUT + t) * NMEL + tid] = acc;
    } else if (tid == NMEL) {
        float acc = gb[0];
        for (int k = 0; k < DDIM + EDIM; k++) acc += xo[k] * gw[k];
        out_gate[b * TOUT + t] = acc;
    }
}

// ---------------- launcher ----------------
extern "C" void kernel_launch(void* const* d_in, const int* in_sizes, int n_in,
                              void* d_out, int out_size) {
    (void)in_sizes; (void)n_in; (void)out_size;
    const float* memory  = (const float*)d_in[0];
    const float* targets = (const float*)d_in[1];
    const unsigned char* mask = (const unsigned char*)d_in[2];
    const float* p1w = (const float*)d_in[3];
    const float* p1b = (const float*)d_in[4];
    const float* p2w = (const float*)d_in[5];
    const float* p2b = (const float*)d_in[6];
    const float* l0k = (const float*)d_in[7];
    const float* l0r = (const float*)d_in[8];
    const float* l0b = (const float*)d_in[9];
    const float* l1k = (const float*)d_in[10];
    const float* l1r = (const float*)d_in[11];
    const float* l1b = (const float*)d_in[12];
    const float* qw  = (const float*)d_in[13];
    const float* qb  = (const float*)d_in[14];
    const float* mw  = (const float*)d_in[15];
    const float* mb  = (const float*)d_in[16];
    const float* vw  = (const float*)d_in[17];
    const float* vb  = (const float*)d_in[18];
    const float* ccw = (const float*)d_in[19];
    const float* ccb = (const float*)d_in[20];
    const float* ldw = (const float*)d_in[21];
    const float* ldb = (const float*)d_in[22];
    const float* pw  = (const float*)d_in[23];
    const float* pb  = (const float*)d_in[24];
    const float* gw  = (const float*)d_in[25];
    const float* gb  = (const float*)d_in[26];

    float* out       = (float*)d_out;
    float* out_mel   = out;                              // [B, TOUT, NMEL]
    float* out_gate  = out + (size_t)BN * TOUT * NMEL;   // [B, TOUT, 1]
    float* out_align = out_gate + (size_t)BN * TOUT;     // [B, TOUT, TIN]

    mask_kernel<<<1, 256>>>(mask);
    prenet_kernel<<<TOUT * BN, 256>>>(targets, p1w, p1b, p2w, p2b);
    keys_kernel<<<BN * TIN, 128>>>(memory, mw, mb);
    decoder_persist<<<NCTA, NTHR>>>(memory, l0k, l0r, l0b, l1k, l1r, l1b,
                                    qw, qb, vw, vb, ccw, ccb, ldw, ldb, out_align);
    proj_kernel<<<TOUT * BN, 128>>>(pw, pb, gw, gb, out_mel, out_gate);
}

// round 5
// speedup vs baseline: 2.1400x; 2.1400x over previous
#include <cuda_runtime.h>
#include <math.h>

#define BN 32
#define TIN 256
#define TOUT 400
#define EDIM 512
#define ADIM 128
#define NFLT 32
#define KSZ 31
#define PRE 256
#define DDIM 1024
#define NMEL 80
#define ZN 4096
#define NCTA 128
#define NTHR 512

// ---------------- persistent device scratch ----------------
__device__ float g_prenet[TOUT * BN * PRE];   // [t][b][k]
__device__ float g_keysT[BN * ADIM * TIN];    // [b][a][t]
__device__ float g_maskneg[BN * TIN];         // 0 or -1e9
__device__ float g_h0[2][BN * DDIM];
__device__ float g_h1[2][BN * DDIM];
__device__ float g_ctx[BN * EDIM];
__device__ float g_wcum[BN * TIN];
__device__ float g_epart[4 * BN * TIN];       // [achunk][b][ti]
__device__ float g_h1all[TOUT * BN * DDIM];   // [t][b][d]
__device__ float g_ctxall[TOUT * BN * EDIM];  // [t][b][e]
__device__ unsigned g_barc;
__device__ volatile unsigned g_barg;

// ---------------- f32x2 helpers ----------------
__device__ __forceinline__ unsigned long long dupf(float w) {
    unsigned long long r;
    asm("mov.b64 %0, {%1, %1};" : "=l"(r) : "f"(w));
    return r;
}
__device__ __forceinline__ void fma2(unsigned long long& acc, unsigned long long x,
                                     unsigned long long w) {
    asm("fma.rn.f32x2 %0, %1, %2, %0;" : "+l"(acc) : "l"(x), "l"(w));
}
__device__ __forceinline__ unsigned long long add2(unsigned long long a,
                                                   unsigned long long b) {
    unsigned long long r;
    asm("add.rn.f32x2 %0, %1, %2;" : "=l"(r) : "l"(a), "l"(b));
    return r;
}
__device__ __forceinline__ void unpack2(float& lo, float& hi, unsigned long long v) {
    asm("mov.b64 {%0, %1}, %2;" : "=f"(lo), "=f"(hi) : "l"(v));
}
__device__ __forceinline__ float sigmoidf_(float x) { return 1.f / (1.f + expf(-x)); }

// ---------------- shared memory union ----------------
struct SmemGemm { float xs[8][32][32]; };                       // 32 KB, [ks][k][row]
struct SmemRed  { unsigned long long red[8][64][8]; float zf[32][32]; };  // 36 KB
struct SmemAttC {
    float wp[TIN + KSZ];
    float cws[KSZ * NFLT];
    float cbs[NFLT];
    float ldws[NFLT * 32];
    float ldbs[32], vws[32];
    float qred[16][32];
    float qp[32];
    float es[2][TIN];
};
struct SmemAttD { float red[256]; float ws[256]; float cred[4][128]; };
union SmemU { SmemGemm g; SmemRed r; SmemAttC c; SmemAttD d; };

// ---------------- grid barrier (sense-reversal, all 128 CTAs resident) --------
__device__ __forceinline__ void grid_bar() {
    __syncthreads();
    if (threadIdx.x == 0) {
        __threadfence();
        unsigned gen = g_barg;
        if (atomicInc(&g_barc, NCTA - 1) == NCTA - 1) {
            g_barg = gen + 1;
            __threadfence();
        } else {
            while (g_barg == gen) __nanosleep(32);
        }
        __threadfence();   // acquire side
    }
    __syncthreads();
}

// ---------------- mask prologue: detect bool-vs-int32 storage, build maskneg --
__global__ void mask_kernel(const unsigned char* __restrict__ mask) {
    __shared__ int s_has;
    int tid = threadIdx.x;
    if (tid == 0) s_has = 0;
    __syncthreads();
    int local = 0;
    for (int i = tid; i < BN * TIN; i += 256)
        if ((i & 3) != 0 && mask[i] != 0) local = 1;
    if (local) atomicOr(&s_has, 1);
    __syncthreads();
    bool is_u8 = (s_has != 0);
    const int* mi = (const int*)mask;
    for (int i = tid; i < BN * TIN; i += 256) {
        int v = is_u8 ? (int)mask[i] : mi[i];
        g_maskneg[i] = v ? 0.f : -1e9f;
    }
}

// ---------------- GEMM: 32 rows x (32 cols owned by CTA) x KTOT ----------------
// 512 threads = 8 k-splits x (8 row-groups x 8 col-slots).
// Thread tile: 4 rows (2 packed f32x2 row-pairs) x 4 cols.
// x staged in smem transposed [ks][k][row]; weights streamed from L2 with a
// per-32k-tile hoisted base pointer; next tile's x prefetched into registers
// before the compute loop (latency hidden under FFMA2 work).
// Result (fp32, fully reduced) lands in sm.r.zf[row][g*8 + dd].
template <int KTOT, int KB0, int KB1, int SA>
__device__ __forceinline__ void gemm_block(SmemU& sm, int jcta,
                                           const float* __restrict__ xA,
                                           const float* __restrict__ xB,
                                           const float* __restrict__ xC,
                                           const float* __restrict__ wK,
                                           const float* __restrict__ wR) {
    constexpr int KC = KTOT / 8;      // per-split K
    constexpr int NT = KC / 32;       // 32-k tiles per split
    const int tid = threadIdx.x;
    const int ks = tid >> 6;          // 0..7 k-split
    const int u = tid & 63;
    const int rg = u >> 3;            // 0..7 -> rows 4rg..4rg+3
    const int ch = u & 7;             // col slot
    const int colbase = 1024 * (ch >> 1) + 8 * jcta + 4 * (ch & 1);
    const int srow = u & 31;          // staging row
    const int shalf = u >> 5;         // staging k-half (16 k each)

    unsigned long long acc[2][4];
    #pragma unroll
    for (int p = 0; p < 2; p++)
        #pragma unroll
        for (int c = 0; c < 4; c++) acc[p][c] = 0ULL;

    float4 st[4];
    // ---- stage-load: fetch 16 x-values (one row, 16 consecutive k) to regs ----
    auto stage_load = [&](int tile) {
        int kg0 = ks * KC + tile * 32 + shalf * 16;   // 16-aligned, never straddles
        const float* src;
        if (kg0 < KB0)      src = xA + srow * SA + kg0;
        else if (kg0 < KB1) src = xB + srow * EDIM + (kg0 - KB0);
        else                src = xC + srow * DDIM + (kg0 - KB1);
        #pragma unroll
        for (int i = 0; i < 4; i++) st[i] = __ldcg((const float4*)src + i);
    };

    stage_load(0);
    for (int tile = 0; tile < NT; tile++) {
        __syncthreads();
        {   // regs -> smem transposed
            int klb = shalf * 16;
            #pragma unroll
            for (int i = 0; i < 4; i++) {
                sm.g.xs[ks][klb + 4 * i + 0][srow] = st[i].x;
                sm.g.xs[ks][klb + 4 * i + 1][srow] = st[i].y;
                sm.g.xs[ks][klb + 4 * i + 2][srow] = st[i].z;
                sm.g.xs[ks][klb + 4 * i + 3][srow] = st[i].w;
            }
        }
        __syncthreads();
        if (tile + 1 < NT) stage_load(tile + 1);   // LDGs fly during compute

        const int k0 = ks * KC + tile * 32;        // whole tile in ONE weight mat
        const float* wrow = ((k0 < KB1) ? wK + (size_t)k0 * ZN
                                        : wR + (size_t)(k0 - KB1) * ZN) + colbase;
        #pragma unroll
        for (int kl = 0; kl < 32; kl++) {
            float4 wv = *(const float4*)(wrow + (size_t)kl * ZN);
            ulonglong2 xv = *(const ulonglong2*)(&sm.g.xs[ks][kl][4 * rg]);
            unsigned long long w0 = dupf(wv.x), w1 = dupf(wv.y);
            unsigned long long w2 = dupf(wv.z), w3 = dupf(wv.w);
            fma2(acc[0][0], xv.x, w0); fma2(acc[1][0], xv.y, w0);
            fma2(acc[0][1], xv.x, w1); fma2(acc[1][1], xv.y, w1);
            fma2(acc[0][2], xv.x, w2); fma2(acc[1][2], xv.y, w2);
            fma2(acc[0][3], xv.x, w3); fma2(acc[1][3], xv.y, w3);
        }
    }
    __syncthreads();
    #pragma unroll
    for (int p = 0; p < 2; p++)
        #pragma unroll
        for (int c = 0; c < 4; c++) sm.r.red[ks][u][p * 4 + c] = acc[p][c];
    __syncthreads();
    {   // cross-split reduction: one u64 output per thread
        int lc = tid & 31, rp = tid >> 5;          // rp: row-pair 0..15
        int gg = lc >> 3, rem = lc & 7, hh = rem >> 2, cc = rem & 3;
        int uo = (rp >> 1) * 8 + 2 * gg + hh;      // owning thread within split
        int slot = (rp & 1) * 4 + cc;
        unsigned long long s = sm.r.red[0][uo][slot];
        #pragma unroll
        for (int k2 = 1; k2 < 8; k2++) s = add2(s, sm.r.red[k2][uo][slot]);
        float lo, hi;
        unpack2(lo, hi, s);
        sm.r.zf[2 * rp][lc]     = lo;
        sm.r.zf[2 * rp + 1][lc] = hi;
    }
    __syncthreads();
}

// ---------------- persistent decoder kernel ----------------
__global__ __launch_bounds__(NTHR, 1) void decoder_persist(
    const float* __restrict__ memory,
    const float* __restrict__ l0k, const float* __restrict__ l0r,
    const float* __restrict__ l0b,
    const float* __restrict__ l1k, const float* __restrict__ l1r,
    const float* __restrict__ l1b,
    const float* __restrict__ qw, const float* __restrict__ qb,
    const float* __restrict__ vw, const float* __restrict__ vb,
    const float* __restrict__ cw, const float* __restrict__ cb,
    const float* __restrict__ ldw, const float* __restrict__ ldb,
    float* __restrict__ out_align) {
    __shared__ SmemU sm;
    const int j = blockIdx.x;
    const int tid = threadIdx.x;

    // ---- init state ----
    {
        int i = j * NTHR + tid;  // 0..65535
        if (i < BN * DDIM) {
            g_h0[0][i] = 0.f; g_h0[1][i] = 0.f;
            g_h1[0][i] = 0.f; g_h1[1][i] = 0.f;
        }
        if (i < BN * EDIM) g_ctx[i] = 0.f;
        if (i < BN * TIN)  g_wcum[i] = 0.f;
    }
    float c0r = 0.f, c1r = 0.f;                // cell state in registers (tid<256)
    const int bq = tid >> 3, dd = tid & 7;     // gate mapping (tid<256): unit (bq, 8j+dd)
    const int du = 8 * j + dd;
    const int ab = j >> 2, ach = j & 3;        // attention mapping

    grid_bar();

    for (int t = 0; t < TOUT; t++) {
        const int rb = t & 1, wb = (t + 1) & 1;

        // ======== phase A: LSTM0 GEMM + gates ========
        gemm_block<1792, 256, 768, PRE>(sm, j, g_prenet + (size_t)t * BN * PRE,
                                        g_ctx, g_h0[rb], l0k, l0r);
        if (tid < 256) {
            float zi  = sm.r.zf[bq][dd]      + l0b[du];
            float zff = sm.r.zf[bq][8 + dd]  + l0b[1024 + du];
            float zg  = sm.r.zf[bq][16 + dd] + l0b[2048 + du];
            float zo  = sm.r.zf[bq][24 + dd] + l0b[3072 + du];
            float ii = sigmoidf_(zi), ff = sigmoidf_(zff), oo = sigmoidf_(zo);
            c0r = ff * c0r + ii * tanhf(zg);
            __stcg(&g_h0[wb][bq * DDIM + du], oo * tanhf(c0r));
        }
        grid_bar();

        // ======== phase B: LSTM1 GEMM + gates ========
        gemm_block<2560, 1024, 1536, DDIM>(sm, j, g_h0[wb], g_ctx, g_h1[rb],
                                           l1k, l1r);
        if (tid < 256) {
            float zi  = sm.r.zf[bq][dd]      + l1b[du];
            float zff = sm.r.zf[bq][8 + dd]  + l1b[1024 + du];
            float zg  = sm.r.zf[bq][16 + dd] + l1b[2048 + du];
            float zo  = sm.r.zf[bq][24 + dd] + l1b[3072 + du];
            float ii = sigmoidf_(zi), ff = sigmoidf_(zff), oo = sigmoidf_(zo);
            c1r = ff * c1r + ii * tanhf(zg);
            float h = oo * tanhf(c1r);
            __stcg(&g_h1[wb][bq * DDIM + du], h);
            g_h1all[((size_t)t * BN + bq) * DDIM + du] = h;
        }
        grid_bar();

        // ======== phase C: attention energies (CTA = b x a-chunk) ========
        {
            const float* h1cur = g_h1[wb];
            {   // qp partials: 16 parts x 64 k
                int al = tid & 31, part = tid >> 5;
                float a0 = 0.f;
                int k0 = part * 64;
                #pragma unroll 4
                for (int k = k0; k < k0 + 64; k++)
                    a0 += __ldcg(h1cur + ab * DDIM + k) * qw[k * ADIM + ach * 32 + al];
                sm.c.qred[part][al] = a0;
            }
            for (int i = tid; i < TIN + KSZ - 1; i += NTHR) {
                int jj = i - (KSZ / 2);
                sm.c.wp[i] = (jj >= 0 && jj < TIN) ? __ldcg(&g_wcum[ab * TIN + jj]) : 0.f;
            }
            for (int i = tid; i < KSZ * NFLT; i += NTHR) sm.c.cws[i] = cw[i];
            if (tid < NFLT) sm.c.cbs[tid] = cb[tid];
            for (int i = tid; i < NFLT * 32; i += NTHR) {
                int f = i >> 5, al = i & 31;
                sm.c.ldws[i] = ldw[f * ADIM + ach * 32 + al];
            }
            if (tid < 32) {
                sm.c.ldbs[tid] = ldb[ach * 32 + tid];
                sm.c.vws[tid]  = vw[ach * 32 + tid];
            }
            __syncthreads();
            if (tid < 32) {
                float s = 0.f;
                #pragma unroll
                for (int p = 0; p < 16; p++) s += sm.c.qred[p][tid];
                sm.c.qp[tid] = s + qb[ach * 32 + tid];
            }
            __syncthreads();
            {   // conv + dense + tanh: (ti, a-half of 16)
                int ti = tid & 255, ah = tid >> 8;
                float locf[NFLT];
                #pragma unroll
                for (int f = 0; f < NFLT; f++) locf[f] = sm.c.cbs[f];
                for (int jk = 0; jk < KSZ; jk++) {
                    float w = sm.c.wp[ti + jk];
                    #pragma unroll
                    for (int f = 0; f < NFLT; f++) locf[f] += w * sm.c.cws[jk * NFLT + f];
                }
                float e = 0.f;
                #pragma unroll 4
                for (int al16 = 0; al16 < 16; al16++) {
                    int al = ah * 16 + al16;
                    int a = ach * 32 + al;
                    float s = sm.c.qp[al] + g_keysT[(ab * ADIM + a) * TIN + ti] +
                              sm.c.ldbs[al];
                    #pragma unroll
                    for (int f = 0; f < NFLT; f++) s += locf[f] * sm.c.ldws[f * 32 + al];
                    e += tanhf(s) * sm.c.vws[al];
                }
                sm.c.es[ah][ti] = e;
            }
            __syncthreads();
            if (tid < 256)
                __stcg(&g_epart[(ach * BN + ab) * TIN + tid],
                       sm.c.es[0][tid] + sm.c.es[1][tid]);
        }
        grid_bar();

        // ======== phase D: softmax + context (CTA = b x E-chunk) ========
        {
            const int ec = ach;
            float ev = 0.f, ex = 0.f;
            if (tid < 256) {
                ev = vb[0] + g_maskneg[ab * TIN + tid];
                #pragma unroll
                for (int ac = 0; ac < 4; ac++)
                    ev += __ldcg(&g_epart[(ac * BN + ab) * TIN + tid]);
                sm.d.red[tid] = ev;
            }
            __syncthreads();
            for (int s = 128; s > 0; s >>= 1) {
                if (tid < s) sm.d.red[tid] = fmaxf(sm.d.red[tid], sm.d.red[tid + s]);
                __syncthreads();
            }
            float mx = sm.d.red[0];
            __syncthreads();
            if (tid < 256) { ex = expf(ev - mx); sm.d.red[tid] = ex; }
            __syncthreads();
            for (int s = 128; s > 0; s >>= 1) {
                if (tid < s) sm.d.red[tid] += sm.d.red[tid + s];
                __syncthreads();
            }
            float inv = 1.f / sm.d.red[0];
            __syncthreads();
            if (tid < 256) {
                float w = ex * inv;
                sm.d.ws[tid] = w;
                if (ec == 0) {
                    __stcg(&g_wcum[ab * TIN + tid],
                           __ldcg(&g_wcum[ab * TIN + tid]) + w);
                    out_align[((size_t)ab * TOUT + t) * TIN + tid] = w;
                }
            }
            __syncthreads();
            {   // context: 128 cols x 4 t-quarters
                int cl = tid & 127, q = tid >> 7;
                float acc = 0.f;
                #pragma unroll 4
                for (int tt = q * 64; tt < q * 64 + 64; tt++)
                    acc += sm.d.ws[tt] *
                           memory[((size_t)ab * TIN + tt) * EDIM + ec * 128 + cl];
                sm.d.cred[q][cl] = acc;
                __syncthreads();
                if (tid < 128) {
                    float cv = sm.d.cred[0][tid] + sm.d.cred[1][tid] +
                               sm.d.cred[2][tid] + sm.d.cred[3][tid];
                    __stcg(&g_ctx[ab * EDIM + ec * 128 + tid], cv);
                    g_ctxall[((size_t)t * BN + ab) * EDIM + ec * 128 + tid] = cv;
                }
            }
        }
        grid_bar();
    }
}

// ---------------- prenet (teacher-forced, fully parallel) ----------------
__global__ void prenet_kernel(const float* __restrict__ targets,
                              const float* __restrict__ w1, const float* __restrict__ b1,
                              const float* __restrict__ w2, const float* __restrict__ b2) {
    int bid = blockIdx.x;          // t*BN + b
    int t = bid >> 5, b = bid & 31;
    __shared__ float xin[NMEL];
    __shared__ float h[PRE];
    int tid = threadIdx.x;         // 256
    if (tid < NMEL) xin[tid] = (t == 0) ? 0.f : targets[(b * TOUT + (t - 1)) * NMEL + tid];
    __syncthreads();
    float acc = b1[tid];
    #pragma unroll 8
    for (int k = 0; k < NMEL; k++) acc += xin[k] * w1[k * PRE + tid];
    h[tid] = fmaxf(acc, 0.f);
    __syncthreads();
    float acc2 = b2[tid];
    #pragma unroll 8
    for (int k = 0; k < PRE; k++) acc2 += h[k] * w2[k * PRE + tid];
    g_prenet[(t * BN + b) * PRE + tid] = fmaxf(acc2, 0.f);
}

// ---------------- keys projection, stored transposed [b][a][t] ----------------
__global__ void keys_kernel(const float* __restrict__ memory,
                            const float* __restrict__ mw, const float* __restrict__ mb) {
    int bid = blockIdx.x;          // b*TIN + t
    int b = bid >> 8, t = bid & 255;
    __shared__ float x[EDIM];
    int tid = threadIdx.x;         // 128
    for (int i = tid; i < EDIM; i += 128) x[i] = memory[(b * TIN + t) * EDIM + i];
    __syncthreads();
    float acc = mb[tid];
    #pragma unroll 8
    for (int k = 0; k < EDIM; k++) acc += x[k] * mw[k * ADIM + tid];
    g_keysT[(b * ADIM + tid) * TIN + t] = acc;
}

// ---------------- output projections (post-pass) ----------------
__global__ void proj_kernel(const float* __restrict__ pw, const float* __restrict__ pb,
                            const float* __restrict__ gw, const float* __restrict__ gb,
                            float* __restrict__ out_mel, float* __restrict__ out_gate) {
    int bid = blockIdx.x;          // t*BN + b
    int t = bid >> 5, b = bid & 31;
    __shared__ float xo[DDIM + EDIM];
    int tid = threadIdx.x;         // 128
    for (int i = tid; i < DDIM; i += 128) xo[i] = g_h1all[(size_t)(t * BN + b) * DDIM + i];
    for (int i = tid; i < EDIM; i += 128) xo[DDIM + i] = g_ctxall[(size_t)(t * BN + b) * EDIM + i];
    __syncthreads();
    if (tid < NMEL) {
        float acc = pb[tid];
        #pragma unroll 8
        for (int k = 0; k < DDIM + EDIM; k++) acc += xo[k] * pw[k * NMEL + tid];
        out_mel[(size_t)(b * TOUT + t) * NMEL + tid] = acc;
    } else if (tid == NMEL) {
        float acc = gb[0];
        for (int k = 0; k < DDIM + EDIM; k++) acc += xo[k] * gw[k];
        out_gate[b * TOUT + t] = acc;
    }
}

// ---------------- launcher ----------------
extern "C" void kernel_launch(void* const* d_in, const int* in_sizes, int n_in,
                              void* d_out, int out_size) {
    (void)in_sizes; (void)n_in; (void)out_size;
    const float* memory  = (const float*)d_in[0];
    const float* targets = (const float*)d_in[1];
    const unsigned char* mask = (const unsigned char*)d_in[2];
    const float* p1w = (const float*)d_in[3];
    const float* p1b = (const float*)d_in[4];
    const float* p2w = (const float*)d_in[5];
    const float* p2b = (const float*)d_in[6];
    const float* l0k = (const float*)d_in[7];
    const float* l0r = (const float*)d_in[8];
    const float* l0b = (const float*)d_in[9];
    const float* l1k = (const float*)d_in[10];
    const float* l1r = (const float*)d_in[11];
    const float* l1b = (const float*)d_in[12];
    const float* qw  = (const float*)d_in[13];
    const float* qb  = (const float*)d_in[14];
    const float* mw  = (const float*)d_in[15];
    const float* mb  = (const float*)d_in[16];
    const float* vw  = (const float*)d_in[17];
    const float* vb  = (const float*)d_in[18];
    const float* ccw = (const float*)d_in[19];
    const float* ccb = (const float*)d_in[20];
    const float* ldw = (const float*)d_in[21];
    const float* ldb = (const float*)d_in[22];
    const float* pw  = (const float*)d_in[23];
    const float* pb  = (const float*)d_in[24];
    const float* gw  = (const float*)d_in[25];
    const float* gb  = (const float*)d_in[26];

    float* out       = (float*)d_out;
    float* out_mel   = out;                              // [B, TOUT, NMEL]
    float* out_gate  = out + (size_t)BN * TOUT * NMEL;   // [B, TOUT, 1]
    float* out_align = out_gate + (size_t)BN * TOUT;     // [B, TOUT, TIN]

    mask_kernel<<<1, 256>>>(mask);
    prenet_kernel<<<TOUT * BN, 256>>>(targets, p1w, p1b, p2w, p2b);
    keys_kernel<<<BN * TIN, 128>>>(memory, mw, mb);
    decoder_persist<<<NCTA, NTHR>>>(memory, l0k, l0r, l0b, l1k, l1r, l1b,
                                    qw, qb, vw, vb, ccw, ccb, ldw, ldb, out_align);
    proj_kernel<<<TOUT * BN, 128>>>(pw, pb, gw, gb, out_mel, out_gate);
}

// round 6
// speedup vs baseline: 2.1407x; 1.0003x over previous
#include <cuda_runtime.h>
#include <math.h>

#define BN 32
#define TIN 256
#define TOUT 400
#define EDIM 512
#define ADIM 128
#define NFLT 32
#define KSZ 31
#define PRE 256
#define DDIM 1024
#define NMEL 80
#define ZN 4096
#define NCTA 128
#define NTHR 512

// ---------------- persistent device scratch ----------------
__device__ float g_prenet[TOUT * BN * PRE];   // [t][b][k]
__device__ float g_keysT[BN * ADIM * TIN];    // [b][a][t]
__device__ float g_maskneg[BN * TIN];         // 0 or -1e9
__device__ float g_h0[2][BN * DDIM];
__device__ float g_h1[2][BN * DDIM];
__device__ float g_ctx[BN * EDIM];
__device__ float g_wcum[BN * TIN];
__device__ float g_epart[4 * BN * TIN];       // [achunk][b][ti]
__device__ float g_h1all[TOUT * BN * DDIM];   // [t][b][d]
__device__ float g_ctxall[TOUT * BN * EDIM];  // [t][b][e]
__device__ unsigned g_barc;
__device__ volatile unsigned g_barg;

// ---------------- f32x2 helpers ----------------
__device__ __forceinline__ unsigned long long dupf(float w) {
    unsigned long long r;
    asm("mov.b64 %0, {%1, %1};" : "=l"(r) : "f"(w));
    return r;
}
__device__ __forceinline__ void fma2(unsigned long long& acc, unsigned long long x,
                                     unsigned long long w) {
    asm("fma.rn.f32x2 %0, %1, %2, %0;" : "+l"(acc) : "l"(x), "l"(w));
}
__device__ __forceinline__ unsigned long long add2(unsigned long long a,
                                                   unsigned long long b) {
    unsigned long long r;
    asm("add.rn.f32x2 %0, %1, %2;" : "=l"(r) : "l"(a), "l"(b));
    return r;
}
__device__ __forceinline__ void unpack2(float& lo, float& hi, unsigned long long v) {
    asm("mov.b64 {%0, %1}, %2;" : "=f"(lo), "=f"(hi) : "l"(v));
}
__device__ __forceinline__ float sigmoidf_(float x) { return 1.f / (1.f + expf(-x)); }

// ---------------- shared memory union ----------------
struct SmemGemm { float xs[8][32][32]; };                       // 32 KB, [ks][k][row]
struct SmemRed  { unsigned long long red[8][64][8]; float zf[32][32]; };  // 36 KB
struct SmemAttC {
    float wp[TIN + KSZ];
    float cws[KSZ * NFLT];
    float cbs[NFLT];
    float ldws[NFLT * 32];
    float ldbs[32], vws[32];
    float qred[16][32];
    float qp[32];
    float es[2][TIN];
};
struct SmemAttD { float red[256]; float ws[256]; float cred[4][128]; };
union SmemU { SmemGemm g; SmemRed r; SmemAttC c; SmemAttD d; };

// ---------------- grid barrier (sense-reversal, all 128 CTAs resident) --------
__device__ __forceinline__ void grid_bar() {
    __syncthreads();
    if (threadIdx.x == 0) {
        __threadfence();
        unsigned gen = g_barg;
        if (atomicInc(&g_barc, NCTA - 1) == NCTA - 1) {
            g_barg = gen + 1;
            __threadfence();
        } else {
            while (g_barg == gen) __nanosleep(32);
        }
        __threadfence();   // acquire side
    }
    __syncthreads();
}

// ---------------- mask prologue: detect bool-vs-int32 storage, build maskneg --
__global__ void mask_kernel(const unsigned char* __restrict__ mask) {
    __shared__ int s_has;
    int tid = threadIdx.x;
    if (tid == 0) s_has = 0;
    __syncthreads();
    int local = 0;
    for (int i = tid; i < BN * TIN; i += 256)
        if ((i & 3) != 0 && mask[i] != 0) local = 1;
    if (local) atomicOr(&s_has, 1);
    __syncthreads();
    bool is_u8 = (s_has != 0);
    const int* mi = (const int*)mask;
    for (int i = tid; i < BN * TIN; i += 256) {
        int v = is_u8 ? (int)mask[i] : mi[i];
        g_maskneg[i] = v ? 0.f : -1e9f;
    }
}

// ---------------- GEMM: 32 rows x (32 cols owned by CTA) x KTOT ----------------
// 512 threads = 8 k-splits x (8 row-groups x 8 col-slots).
// Thread tile: 4 rows (2 packed f32x2 row-pairs) x 4 cols.
// x staged in smem transposed [ks][k][row]; weights streamed from L2 with a
// per-32k-tile hoisted base pointer; next tile's x prefetched into registers
// before the compute loop (latency hidden under FFMA2 work).
// Result (fp32, fully reduced) lands in sm.r.zf[row][g*8 + dd].
template <int KTOT, int KB0, int KB1, int SA>
__device__ __forceinline__ void gemm_block(SmemU& sm, int jcta,
                                           const float* __restrict__ xA,
                                           const float* __restrict__ xB,
                                           const float* __restrict__ xC,
                                           const float* __restrict__ wK,
                                           const float* __restrict__ wR) {
    constexpr int KC = KTOT / 8;      // per-split K
    constexpr int NT = KC / 32;       // 32-k tiles per split
    const int tid = threadIdx.x;
    const int ks = tid >> 6;          // 0..7 k-split
    const int u = tid & 63;
    const int rg = u >> 3;            // 0..7 -> rows 4rg..4rg+3
    const int ch = u & 7;             // col slot
    const int colbase = 1024 * (ch >> 1) + 8 * jcta + 4 * (ch & 1);
    const int srow = u & 31;          // staging row
    const int shalf = u >> 5;         // staging k-half (16 k each)

    unsigned long long acc[2][4];
    #pragma unroll
    for (int p = 0; p < 2; p++)
        #pragma unroll
        for (int c = 0; c < 4; c++) acc[p][c] = 0ULL;

    float4 st[4];
    // ---- stage-load: fetch 16 x-values (one row, 16 consecutive k) to regs ----
    auto stage_load = [&](int tile) {
        int kg0 = ks * KC + tile * 32 + shalf * 16;   // 16-aligned, never straddles
        const float* src;
        if (kg0 < KB0)      src = xA + srow * SA + kg0;
        else if (kg0 < KB1) src = xB + srow * EDIM + (kg0 - KB0);
        else                src = xC + srow * DDIM + (kg0 - KB1);
        #pragma unroll
        for (int i = 0; i < 4; i++) st[i] = __ldcg((const float4*)src + i);
    };

    stage_load(0);
    for (int tile = 0; tile < NT; tile++) {
        __syncthreads();
        {   // regs -> smem transposed
            int klb = shalf * 16;
            #pragma unroll
            for (int i = 0; i < 4; i++) {
                sm.g.xs[ks][klb + 4 * i + 0][srow] = st[i].x;
                sm.g.xs[ks][klb + 4 * i + 1][srow] = st[i].y;
                sm.g.xs[ks][klb + 4 * i + 2][srow] = st[i].z;
                sm.g.xs[ks][klb + 4 * i + 3][srow] = st[i].w;
            }
        }
        __syncthreads();
        if (tile + 1 < NT) stage_load(tile + 1);   // LDGs fly during compute

        const int k0 = ks * KC + tile * 32;        // whole tile in ONE weight mat
        const float* wrow = ((k0 < KB1) ? wK + (size_t)k0 * ZN
                                        : wR + (size_t)(k0 - KB1) * ZN) + colbase;
        #pragma unroll
        for (int kl = 0; kl < 32; kl++) {
            float4 wv = *(const float4*)(wrow + (size_t)kl * ZN);
            ulonglong2 xv = *(const ulonglong2*)(&sm.g.xs[ks][kl][4 * rg]);
            unsigned long long w0 = dupf(wv.x), w1 = dupf(wv.y);
            unsigned long long w2 = dupf(wv.z), w3 = dupf(wv.w);
            fma2(acc[0][0], xv.x, w0); fma2(acc[1][0], xv.y, w0);
            fma2(acc[0][1], xv.x, w1); fma2(acc[1][1], xv.y, w1);
            fma2(acc[0][2], xv.x, w2); fma2(acc[1][2], xv.y, w2);
            fma2(acc[0][3], xv.x, w3); fma2(acc[1][3], xv.y, w3);
        }
    }
    __syncthreads();
    #pragma unroll
    for (int p = 0; p < 2; p++)
        #pragma unroll
        for (int c = 0; c < 4; c++) sm.r.red[ks][u][p * 4 + c] = acc[p][c];
    __syncthreads();
    {   // cross-split reduction: one u64 output per thread
        int lc = tid & 31, rp = tid >> 5;          // rp: row-pair 0..15
        int gg = lc >> 3, rem = lc & 7, hh = rem >> 2, cc = rem & 3;
        int uo = (rp >> 1) * 8 + 2 * gg + hh;      // owning thread within split
        int slot = (rp & 1) * 4 + cc;
        unsigned long long s = sm.r.red[0][uo][slot];
        #pragma unroll
        for (int k2 = 1; k2 < 8; k2++) s = add2(s, sm.r.red[k2][uo][slot]);
        float lo, hi;
        unpack2(lo, hi, s);
        sm.r.zf[2 * rp][lc]     = lo;
        sm.r.zf[2 * rp + 1][lc] = hi;
    }
    __syncthreads();
}

// ---------------- persistent decoder kernel ----------------
__global__ __launch_bounds__(NTHR, 1) void decoder_persist(
    const float* __restrict__ memory,
    const float* __restrict__ l0k, const float* __restrict__ l0r,
    const float* __restrict__ l0b,
    const float* __restrict__ l1k, const float* __restrict__ l1r,
    const float* __restrict__ l1b,
    const float* __restrict__ qw, const float* __restrict__ qb,
    const float* __restrict__ vw, const float* __restrict__ vb,
    const float* __restrict__ cw, const float* __restrict__ cb,
    const float* __restrict__ ldw, const float* __restrict__ ldb,
    float* __restrict__ out_align) {
    __shared__ SmemU sm;
    const int j = blockIdx.x;
    const int tid = threadIdx.x;

    // ---- init state ----
    {
        int i = j * NTHR + tid;  // 0..65535
        if (i < BN * DDIM) {
            g_h0[0][i] = 0.f; g_h0[1][i] = 0.f;
            g_h1[0][i] = 0.f; g_h1[1][i] = 0.f;
        }
        if (i < BN * EDIM) g_ctx[i] = 0.f;
        if (i < BN * TIN)  g_wcum[i] = 0.f;
    }
    float c0r = 0.f, c1r = 0.f;                // cell state in registers (tid<256)
    const int bq = tid >> 3, dd = tid & 7;     // gate mapping (tid<256): unit (bq, 8j+dd)
    const int du = 8 * j + dd;
    const int ab = j >> 2, ach = j & 3;        // attention mapping

    grid_bar();

    for (int t = 0; t < TOUT; t++) {
        const int rb = t & 1, wb = (t + 1) & 1;

        // ======== phase A: LSTM0 GEMM + gates ========
        gemm_block<1792, 256, 768, PRE>(sm, j, g_prenet + (size_t)t * BN * PRE,
                                        g_ctx, g_h0[rb], l0k, l0r);
        if (tid < 256) {
            float zi  = sm.r.zf[bq][dd]      + l0b[du];
            float zff = sm.r.zf[bq][8 + dd]  + l0b[1024 + du];
            float zg  = sm.r.zf[bq][16 + dd] + l0b[2048 + du];
            float zo  = sm.r.zf[bq][24 + dd] + l0b[3072 + du];
            float ii = sigmoidf_(zi), ff = sigmoidf_(zff), oo = sigmoidf_(zo);
            c0r = ff * c0r + ii * tanhf(zg);
            __stcg(&g_h0[wb][bq * DDIM + du], oo * tanhf(c0r));
        }
        grid_bar();

        // ======== phase B: LSTM1 GEMM + gates ========
        gemm_block<2560, 1024, 1536, DDIM>(sm, j, g_h0[wb], g_ctx, g_h1[rb],
                                           l1k, l1r);
        if (tid < 256) {
            float zi  = sm.r.zf[bq][dd]      + l1b[du];
            float zff = sm.r.zf[bq][8 + dd]  + l1b[1024 + du];
            float zg  = sm.r.zf[bq][16 + dd] + l1b[2048 + du];
            float zo  = sm.r.zf[bq][24 + dd] + l1b[3072 + du];
            float ii = sigmoidf_(zi), ff = sigmoidf_(zff), oo = sigmoidf_(zo);
            c1r = ff * c1r + ii * tanhf(zg);
            float h = oo * tanhf(c1r);
            __stcg(&g_h1[wb][bq * DDIM + du], h);
            g_h1all[((size_t)t * BN + bq) * DDIM + du] = h;
        }
        grid_bar();

        // ======== phase C: attention energies (CTA = b x a-chunk) ========
        {
            const float* h1cur = g_h1[wb];
            {   // qp partials: 16 parts x 64 k
                int al = tid & 31, part = tid >> 5;
                float a0 = 0.f;
                int k0 = part * 64;
                #pragma unroll 4
                for (int k = k0; k < k0 + 64; k++)
                    a0 += __ldcg(h1cur + ab * DDIM + k) * qw[k * ADIM + ach * 32 + al];
                sm.c.qred[part][al] = a0;
            }
            for (int i = tid; i < TIN + KSZ - 1; i += NTHR) {
                int jj = i - (KSZ / 2);
                sm.c.wp[i] = (jj >= 0 && jj < TIN) ? __ldcg(&g_wcum[ab * TIN + jj]) : 0.f;
            }
            for (int i = tid; i < KSZ * NFLT; i += NTHR) sm.c.cws[i] = cw[i];
            if (tid < NFLT) sm.c.cbs[tid] = cb[tid];
            for (int i = tid; i < NFLT * 32; i += NTHR) {
                int f = i >> 5, al = i & 31;
                sm.c.ldws[i] = ldw[f * ADIM + ach * 32 + al];
            }
            if (tid < 32) {
                sm.c.ldbs[tid] = ldb[ach * 32 + tid];
                sm.c.vws[tid]  = vw[ach * 32 + tid];
            }
            __syncthreads();
            if (tid < 32) {
                float s = 0.f;
                #pragma unroll
                for (int p = 0; p < 16; p++) s += sm.c.qred[p][tid];
                sm.c.qp[tid] = s + qb[ach * 32 + tid];
            }
            __syncthreads();
            {   // conv + dense + tanh: (ti, a-half of 16)
                int ti = tid & 255, ah = tid >> 8;
                float locf[NFLT];
                #pragma unroll
                for (int f = 0; f < NFLT; f++) locf[f] = sm.c.cbs[f];
                for (int jk = 0; jk < KSZ; jk++) {
                    float w = sm.c.wp[ti + jk];
                    #pragma unroll
                    for (int f = 0; f < NFLT; f++) locf[f] += w * sm.c.cws[jk * NFLT + f];
                }
                float e = 0.f;
                #pragma unroll 4
                for (int al16 = 0; al16 < 16; al16++) {
                    int al = ah * 16 + al16;
                    int a = ach * 32 + al;
                    float s = sm.c.qp[al] + g_keysT[(ab * ADIM + a) * TIN + ti] +
                              sm.c.ldbs[al];
                    #pragma unroll
                    for (int f = 0; f < NFLT; f++) s += locf[f] * sm.c.ldws[f * 32 + al];
                    e += tanhf(s) * sm.c.vws[al];
                }
                sm.c.es[ah][ti] = e;
            }
            __syncthreads();
            if (tid < 256)
                __stcg(&g_epart[(ach * BN + ab) * TIN + tid],
                       sm.c.es[0][tid] + sm.c.es[1][tid]);
        }
        grid_bar();

        // ======== phase D: softmax + context (CTA = b x E-chunk) ========
        {
            const int ec = ach;
            float ev = 0.f, ex = 0.f;
            if (tid < 256) {
                ev = vb[0] + g_maskneg[ab * TIN + tid];
                #pragma unroll
                for (int ac = 0; ac < 4; ac++)
                    ev += __ldcg(&g_epart[(ac * BN + ab) * TIN + tid]);
                sm.d.red[tid] = ev;
            }
            __syncthreads();
            for (int s = 128; s > 0; s >>= 1) {
                if (tid < s) sm.d.red[tid] = fmaxf(sm.d.red[tid], sm.d.red[tid + s]);
                __syncthreads();
            }
            float mx = sm.d.red[0];
            __syncthreads();
            if (tid < 256) { ex = expf(ev - mx); sm.d.red[tid] = ex; }
            __syncthreads();
            for (int s = 128; s > 0; s >>= 1) {
                if (tid < s) sm.d.red[tid] += sm.d.red[tid + s];
                __syncthreads();
            }
            float inv = 1.f / sm.d.red[0];
            __syncthreads();
            if (tid < 256) {
                float w = ex * inv;
                sm.d.ws[tid] = w;
                if (ec == 0) {
                    __stcg(&g_wcum[ab * TIN + tid],
                           __ldcg(&g_wcum[ab * TIN + tid]) + w);
                    out_align[((size_t)ab * TOUT + t) * TIN + tid] = w;
                }
            }
            __syncthreads();
            {   // context: 128 cols x 4 t-quarters
                int cl = tid & 127, q = tid >> 7;
                float acc = 0.f;
                #pragma unroll 4
                for (int tt = q * 64; tt < q * 64 + 64; tt++)
                    acc += sm.d.ws[tt] *
                           memory[((size_t)ab * TIN + tt) * EDIM + ec * 128 + cl];
                sm.d.cred[q][cl] = acc;
                __syncthreads();
                if (tid < 128) {
                    float cv = sm.d.cred[0][tid] + sm.d.cred[1][tid] +
                               sm.d.cred[2][tid] + sm.d.cred[3][tid];
                    __stcg(&g_ctx[ab * EDIM + ec * 128 + tid], cv);
                    g_ctxall[((size_t)t * BN + ab) * EDIM + ec * 128 + tid] = cv;
                }
            }
        }
        grid_bar();
    }
}

// ---------------- prenet (teacher-forced, fully parallel) ----------------
__global__ void prenet_kernel(const float* __restrict__ targets,
                              const float* __restrict__ w1, const float* __restrict__ b1,
                              const float* __restrict__ w2, const float* __restrict__ b2) {
    int bid = blockIdx.x;          // t*BN + b
    int t = bid >> 5, b = bid & 31;
    __shared__ float xin[NMEL];
    __shared__ float h[PRE];
    int tid = threadIdx.x;         // 256
    if (tid < NMEL) xin[tid] = (t == 0) ? 0.f : targets[(b * TOUT + (t - 1)) * NMEL + tid];
    __syncthreads();
    float acc = b1[tid];
    #pragma unroll 8
    for (int k = 0; k < NMEL; k++) acc += xin[k] * w1[k * PRE + tid];
    h[tid] = fmaxf(acc, 0.f);
    __syncthreads();
    float acc2 = b2[tid];
    #pragma unroll 8
    for (int k = 0; k < PRE; k++) acc2 += h[k] * w2[k * PRE + tid];
    g_prenet[(t * BN + b) * PRE + tid] = fmaxf(acc2, 0.f);
}

// ---------------- keys projection, stored transposed [b][a][t] ----------------
__global__ void keys_kernel(const float* __restrict__ memory,
                            const float* __restrict__ mw, const float* __restrict__ mb) {
    int bid = blockIdx.x;          // b*TIN + t
    int b = bid >> 8, t = bid & 255;
    __shared__ float x[EDIM];
    int tid = threadIdx.x;         // 128
    for (int i = tid; i < EDIM; i += 128) x[i] = memory[(b * TIN + t) * EDIM + i];
    __syncthreads();
    float acc = mb[tid];
    #pragma unroll 8
    for (int k = 0; k < EDIM; k++) acc += x[k] * mw[k * ADIM + tid];
    g_keysT[(b * ADIM + tid) * TIN + t] = acc;
}

// ---------------- output projections (post-pass) ----------------
__global__ void proj_kernel(const float* __restrict__ pw, const float* __restrict__ pb,
                            const float* __restrict__ gw, const float* __restrict__ gb,
                            float* __restrict__ out_mel, float* __restrict__ out_gate) {
    int bid = blockIdx.x;          // t*BN + b
    int t = bid >> 5, b = bid & 31;
    __shared__ float xo[DDIM + EDIM];
    int tid = threadIdx.x;         // 128
    for (int i = tid; i < DDIM; i += 128) xo[i] = g_h1all[(size_t)(t * BN + b) * DDIM + i];
    for (int i = tid; i < EDIM; i += 128) xo[DDIM + i] = g_ctxall[(size_t)(t * BN + b) * EDIM + i];
    __syncthreads();
    if (tid < NMEL) {
        float acc = pb[tid];
        #pragma unroll 8
        for (int k = 0; k < DDIM + EDIM; k++) acc += xo[k] * pw[k * NMEL + tid];
        out_mel[(size_t)(b * TOUT + t) * NMEL + tid] = acc;
    } else if (tid == NMEL) {
        float acc = gb[0];
        for (int k = 0; k < DDIM + EDIM; k++) acc += xo[k] * gw[k];
        out_gate[b * TOUT + t] = acc;
    }
}

// ---------------- launcher ----------------
extern "C" void kernel_launch(void* const* d_in, const int* in_sizes, int n_in,
                              void* d_out, int out_size) {
    (void)in_sizes; (void)n_in; (void)out_size;
    const float* memory  = (const float*)d_in[0];
    const float* targets = (const float*)d_in[1];
    const unsigned char* mask = (const unsigned char*)d_in[2];
    const float* p1w = (const float*)d_in[3];
    const float* p1b = (const float*)d_in[4];
    const float* p2w = (const float*)d_in[5];
    const float* p2b = (const float*)d_in[6];
    const float* l0k = (const float*)d_in[7];
    const float* l0r = (const float*)d_in[8];
    const float* l0b = (const float*)d_in[9];
    const float* l1k = (const float*)d_in[10];
    const float* l1r = (const float*)d_in[11];
    const float* l1b = (const float*)d_in[12];
    const float* qw  = (const float*)d_in[13];
    const float* qb  = (const float*)d_in[14];
    const float* mw  = (const float*)d_in[15];
    const float* mb  = (const float*)d_in[16];
    const float* vw  = (const float*)d_in[17];
    const float* vb  = (const float*)d_in[18];
    const float* ccw = (const float*)d_in[19];
    const float* ccb = (const float*)d_in[20];
    const float* ldw = (const float*)d_in[21];
    const float* ldb = (const float*)d_in[22];
    const float* pw  = (const float*)d_in[23];
    const float* pb  = (const float*)d_in[24];
    const float* gw  = (const float*)d_in[25];
    const float* gb  = (const float*)d_in[26];

    float* out       = (float*)d_out;
    float* out_mel   = out;                              // [B, TOUT, NMEL]
    float* out_gate  = out + (size_t)BN * TOUT * NMEL;   // [B, TOUT, 1]
    float* out_align = out_gate + (size_t)BN * TOUT;     // [B, TOUT, TIN]

    mask_kernel<<<1, 256>>>(mask);
    prenet_kernel<<<TOUT * BN, 256>>>(targets, p1w, p1b, p2w, p2b);
    keys_kernel<<<BN * TIN, 128>>>(memory, mw, mb);
    decoder_persist<<<NCTA, NTHR>>>(memory, l0k, l0r, l0b, l1k, l1r, l1b,
                                    qw, qb, vw, vb, ccw, ccb, ldw, ldb, out_align);
    proj_kernel<<<TOUT * BN, 128>>>(pw, pb, gw, gb, out_mel, out_gate);
}

// round 7
// speedup vs baseline: 2.6688x; 1.2467x over previous
#include <cuda_runtime.h>
#include <cuda_bf16.h>
#include <math.h>
#include <string.h>

#define BN 32
#define TIN 256
#define TOUT 400
#define EDIM 512
#define ADIM 128
#define NFLT 32
#define KSZ 31
#define PRE 256
#define DDIM 1024
#define NMEL 80
#define ZN 4096
#define NCTA 128
#define NTHR 512
#define CHUNKK 128
#define KSPC 8                 // ksteps (16k) per chunk
#define KST0 112               // 1792/16
#define KST1 160               // 2560/16
#define DSMEM_BYTES 104448     // 64K Bbuf + 34816 x + 4096 zf

// ---------------- persistent device scratch ----------------
__device__ float g_prenet[TOUT * BN * PRE];   // [t][b][k]
__device__ float g_keysT[BN * ADIM * TIN];    // [b][a][t]
__device__ float g_maskneg[BN * TIN];         // 0 or -1e9
__device__ float g_h0[2][BN * DDIM];
__device__ float g_h1[2][BN * DDIM];
__device__ float g_ctx[BN * EDIM];
__device__ float g_wcum[BN * TIN];
__device__ float g_epart[4 * BN * TIN];       // [achunk][b][ti]
__device__ float g_h1all[TOUT * BN * DDIM];   // [t][b][d]
__device__ float g_ctxall[TOUT * BN * EDIM];  // [t][b][e]
__device__ unsigned g_barc;
__device__ volatile unsigned g_barg;
// packed bf16 hi/lo weights in mma fragment order:
// [j][kstep][g][lane] : uint4 = {bh0, bh1, bl0, bl1}
__device__ uint4 g_pb0[(size_t)NCTA * KST0 * 4 * 32];
__device__ uint4 g_pb1[(size_t)NCTA * KST1 * 4 * 32];

__device__ __forceinline__ float sigmoidf_(float x) { return 1.f / (1.f + expf(-x)); }

__device__ __forceinline__ unsigned smem_u32(const void* p) {
    unsigned a;
    asm("{ .reg .u64 t; cvta.to.shared.u64 t, %1; cvt.u32.u64 %0, t; }"
        : "=r"(a) : "l"(p));
    return a;
}
__device__ __forceinline__ void cpasync16(unsigned dst, const void* src) {
    asm volatile("cp.async.cg.shared.global [%0], [%1], 16;" :: "r"(dst), "l"(src));
}
#define CP_COMMIT() asm volatile("cp.async.commit_group;" ::: "memory")
#define CP_WAITG(n) asm volatile("cp.async.wait_group %0;" :: "n"(n) : "memory")

__device__ __forceinline__ unsigned pk2(__nv_bfloat16 a, __nv_bfloat16 b) {
    __nv_bfloat162 t(a, b);
    unsigned r;
    memcpy(&r, &t, 4);
    return r;
}
__device__ __forceinline__ void mma16816(float& d0, float& d1, float& d2, float& d3,
                                         unsigned a0, unsigned a1, unsigned a2,
                                         unsigned a3, unsigned b0, unsigned b1) {
    asm volatile("mma.sync.aligned.m16n8k16.row.col.f32.bf16.bf16.f32 "
                 "{%0,%1,%2,%3}, {%4,%5,%6,%7}, {%8,%9}, {%0,%1,%2,%3};"
                 : "+f"(d0), "+f"(d1), "+f"(d2), "+f"(d3)
                 : "r"(a0), "r"(a1), "r"(a2), "r"(a3), "r"(b0), "r"(b1));
}

// ---------------- grid barrier ----------------
__device__ __forceinline__ void grid_bar() {
    __syncthreads();
    if (threadIdx.x == 0) {
        __threadfence();
        unsigned gen = g_barg;
        if (atomicInc(&g_barc, NCTA - 1) == NCTA - 1) {
            g_barg = gen + 1;
            __threadfence();
        } else {
            while (g_barg == gen) __nanosleep(32);
        }
        __threadfence();
    }
    __syncthreads();
}

// ---------------- attention smem structs (alias the gemm region) ------------
struct AttC {
    float wp[TIN + KSZ];
    float cws[KSZ * NFLT];
    float cbs[NFLT];
    float ldws[NFLT * 32];
    float ldbs[32], vws[32];
    float qred[16][32];
    float qp[32];
    float es[2][TIN];
    float loc[TIN][NFLT + 1];   // padded: conflict-free column reads
};
struct AttD { float red[256]; float ws[256]; float cred[4][128]; };

// ---------------- mask prologue ----------------
__global__ void mask_kernel(const unsigned char* __restrict__ mask) {
    __shared__ int s_has;
    int tid = threadIdx.x;
    if (tid == 0) s_has = 0;
    __syncthreads();
    int local = 0;
    for (int i = tid; i < BN * TIN; i += 256)
        if ((i & 3) != 0 && mask[i] != 0) local = 1;
    if (local) atomicOr(&s_has, 1);
    __syncthreads();
    bool is_u8 = (s_has != 0);
    const int* mi = (const int*)mask;
    for (int i = tid; i < BN * TIN; i += 256) {
        int v = is_u8 ? (int)mask[i] : mi[i];
        g_maskneg[i] = v ? 0.f : -1e9f;
    }
}

// ---------------- weight pack: fp32 [k][4096] -> fragment-order bf16 hi/lo ---
template <int KST, int KB1>
__global__ void pack_kernel(const float* __restrict__ wK, const float* __restrict__ wR,
                            uint4* __restrict__ out) {
    int ks = blockIdx.x, nb = blockIdx.y;
    __shared__ float w[16][128];
    int k0 = ks * 16;
    const float* W = (k0 < KB1) ? wK + (size_t)k0 * ZN : wR + (size_t)(k0 - KB1) * ZN;
    int N0 = nb * 128;
    for (int i = threadIdx.x; i < 2048; i += 256) {
        int kk = i >> 7, n = i & 127;
        w[kk][n] = W[(size_t)kk * ZN + N0 + n];
    }
    __syncthreads();
    int g = N0 >> 10, jbase = (N0 & 1023) >> 3;
    for (int s = threadIdx.x; s < 512; s += 256) {
        int jl = s >> 5, lane = s & 31;
        int q = lane & 3, t4 = lane >> 2;
        int n = jl * 8 + t4;
        float v0 = w[2 * q][n], v1 = w[2 * q + 1][n];
        float v2 = w[2 * q + 8][n], v3 = w[2 * q + 9][n];
        __nv_bfloat16 h0 = __float2bfloat16_rn(v0), h1 = __float2bfloat16_rn(v1);
        __nv_bfloat16 h2 = __float2bfloat16_rn(v2), h3 = __float2bfloat16_rn(v3);
        unsigned bh0 = pk2(h0, h1), bh1 = pk2(h2, h3);
        unsigned bl0 = pk2(__float2bfloat16_rn(v0 - __bfloat162float(h0)),
                           __float2bfloat16_rn(v1 - __bfloat162float(h1)));
        unsigned bl1 = pk2(__float2bfloat16_rn(v2 - __bfloat162float(h2)),
                           __float2bfloat16_rn(v3 - __bfloat162float(h3)));
        int j = jbase + jl;
        out[((size_t)(j * KST + ks) * 4 + g) * 32 + lane] = make_uint4(bh0, bh1, bl0, bl1);
    }
}

// ---------------- warp-specialized bf16 MMA GEMM --------------------------
// rows = 32 batch; cols = CTA j's 32 units-by-gates {1024g + 8j + i}.
// warps 0..7 consumers (mi = w&1, g = w>>1); warps 8..15 producers.
// zf[row*32 + 8g + i] gets the fully-reduced fp32 result.
template <int KTOT, int KB0, int KB1, int SA>
__device__ __forceinline__ void gemm_mma(char* dsm, int j,
                                         const float* __restrict__ xA,
                                         const float* __restrict__ xB,
                                         const float* __restrict__ xC,
                                         const uint4* __restrict__ pB,
                                         float* __restrict__ zf) {
    constexpr int NC = KTOT / CHUNKK;
    constexpr int KST = KTOT / 16;
    const int tid = threadIdx.x;
    uint4* Bb = (uint4*)dsm;                                   // [4][KSPC][4][32]
    __nv_bfloat16* xh = (__nv_bfloat16*)(dsm + 65536);         // [2][32][136]
    __nv_bfloat16* xl = xh + 2 * 32 * 136;

    if (tid >= 256) {
        // =============== producers ===============
        const int p = tid - 256;
        const int row = p >> 3, kseg = p & 7;
        float4 xr[2][4];
        auto ldgx = [&](int c, int set) {
            int k0 = c * CHUNKK + kseg * 16;
            const float* s;
            if (k0 < KB0)      s = xA + row * SA + k0;
            else if (k0 < KB1) s = xB + row * EDIM + (k0 - KB0);
            else               s = xC + row * DDIM + (k0 - KB1);
            #pragma unroll
            for (int i = 0; i < 4; i++) xr[set][i] = __ldcg((const float4*)s + i);
        };
        auto stsx = [&](int c, int set) {
            int bx = c & 1;
            __nv_bfloat16* dh = xh + bx * 4352 + row * 136 + kseg * 16;
            __nv_bfloat16* dl = xl + bx * 4352 + row * 136 + kseg * 16;
            float f[16];
            #pragma unroll
            for (int i = 0; i < 4; i++) {
                f[4 * i] = xr[set][i].x;     f[4 * i + 1] = xr[set][i].y;
                f[4 * i + 2] = xr[set][i].z; f[4 * i + 3] = xr[set][i].w;
            }
            #pragma unroll
            for (int u = 0; u < 8; u++) {
                float a = f[2 * u], b = f[2 * u + 1];
                __nv_bfloat16 ha = __float2bfloat16_rn(a), hb = __float2bfloat16_rn(b);
                ((unsigned*)dh)[u] = pk2(ha, hb);
                ((unsigned*)dl)[u] =
                    pk2(__float2bfloat16_rn(a - __bfloat162float(ha)),
                        __float2bfloat16_rn(b - __bfloat162float(hb)));
            }
        };
        auto cpB = [&](int c) {
            int buf = c & 3;
            const char* src = (const char*)(pB + (size_t)(j * KST + c * KSPC) * 4 * 32);
            char* dst = (char*)(Bb + (size_t)buf * 1024);
            #pragma unroll
            for (int i = 0; i < 4; i++)
                cpasync16(smem_u32(dst + i * 4096 + p * 16), src + i * 4096 + p * 16);
            CP_COMMIT();
        };

        ldgx(0, 0); ldgx(1, 1);
        cpB(0); cpB(1); cpB(2);
        stsx(0, 0);
        ldgx(2, 0);
        CP_WAITG(2);               // B(0) landed
        __syncthreads();
        for (int c = 0; c < NC; c++) {
            if (c + 1 < NC) stsx(c + 1, (c + 1) & 1);
            if (c + 3 < NC) { ldgx(c + 3, (c + 1) & 1); cpB(c + 3); CP_WAITG(2); }
            else if (c + 2 < NC) CP_WAITG(1);
            else if (c + 1 < NC) CP_WAITG(0);
            __syncthreads();
        }
    } else {
        // =============== consumers ===============
        const int w = tid >> 5, lane = tid & 31;
        const int mi = w & 1, g = w >> 1;
        const int t4 = lane >> 2, q = lane & 3;
        const int r0 = mi * 16 + t4;
        float d0 = 0.f, d1 = 0.f, d2 = 0.f, d3 = 0.f;
        __syncthreads();
        for (int c = 0; c < NC; c++) {
            const uint4* Bw = Bb + (c & 3) * 1024 + g * 32 + lane;
            const __nv_bfloat16* xhb = xh + (c & 1) * 4352;
            const __nv_bfloat16* xlb = xl + (c & 1) * 4352;
            #pragma unroll
            for (int ks = 0; ks < KSPC; ks++) {
                int kb = ks * 16 + 2 * q;
                unsigned a0 = *(const unsigned*)(xhb + r0 * 136 + kb);
                unsigned a1 = *(const unsigned*)(xhb + (r0 + 8) * 136 + kb);
                unsigned a2 = *(const unsigned*)(xhb + r0 * 136 + kb + 8);
                unsigned a3 = *(const unsigned*)(xhb + (r0 + 8) * 136 + kb + 8);
                unsigned l0 = *(const unsigned*)(xlb + r0 * 136 + kb);
                unsigned l1 = *(const unsigned*)(xlb + (r0 + 8) * 136 + kb);
                unsigned l2 = *(const unsigned*)(xlb + r0 * 136 + kb + 8);
                unsigned l3 = *(const unsigned*)(xlb + (r0 + 8) * 136 + kb + 8);
                uint4 B = Bw[ks * 128];
                mma16816(d0, d1, d2, d3, a0, a1, a2, a3, B.x, B.y);   // Ah*Bh
                mma16816(d0, d1, d2, d3, l0, l1, l2, l3, B.x, B.y);   // Al*Bh
                mma16816(d0, d1, d2, d3, a0, a1, a2, a3, B.z, B.w);   // Ah*Bl
            }
            __syncthreads();
        }
        zf[r0 * 32 + g * 8 + 2 * q]           = d0;
        zf[r0 * 32 + g * 8 + 2 * q + 1]       = d1;
        zf[(r0 + 8) * 32 + g * 8 + 2 * q]     = d2;
        zf[(r0 + 8) * 32 + g * 8 + 2 * q + 1] = d3;
    }
    __syncthreads();   // publish zf
}

// ---------------- persistent decoder kernel ----------------
__global__ __launch_bounds__(NTHR, 1) void decoder_persist(
    const float* __restrict__ memory,
    const float* __restrict__ l0b, const float* __restrict__ l1b,
    const float* __restrict__ qw, const float* __restrict__ qb,
    const float* __restrict__ vw, const float* __restrict__ vb,
    const float* __restrict__ cw, const float* __restrict__ cb,
    const float* __restrict__ ldw, const float* __restrict__ ldb,
    float* __restrict__ out_align) {
    extern __shared__ char dsm[];
    float* zf = (float*)(dsm + 100352);
    AttC* sc = (AttC*)dsm;
    AttD* sd = (AttD*)dsm;
    const int j = blockIdx.x;
    const int tid = threadIdx.x;

    {   // init state
        int i = j * NTHR + tid;
        if (i < BN * DDIM) {
            g_h0[0][i] = 0.f; g_h0[1][i] = 0.f;
            g_h1[0][i] = 0.f; g_h1[1][i] = 0.f;
        }
        if (i < BN * EDIM) g_ctx[i] = 0.f;
        if (i < BN * TIN)  g_wcum[i] = 0.f;
    }
    float c0r = 0.f, c1r = 0.f;              // cell state in regs (tid<256)
    const int bq = tid >> 3, dd = tid & 7;   // gate mapping: unit (bq, 8j+dd)
    const int du = 8 * j + dd;
    const int ab = j >> 2, ach = j & 3;      // attention mapping

    grid_bar();

    for (int t = 0; t < TOUT; t++) {
        const int rb = t & 1, wb = (t + 1) & 1;

        // ======== phase A: LSTM0 GEMM + gates ========
        gemm_mma<1792, 256, 768, PRE>(dsm, j, g_prenet + (size_t)t * BN * PRE,
                                      g_ctx, g_h0[rb], g_pb0, zf);
        if (tid < 256) {
            float zi  = zf[bq * 32 + dd]      + l0b[du];
            float zff = zf[bq * 32 + 8 + dd]  + l0b[1024 + du];
            float zg  = zf[bq * 32 + 16 + dd] + l0b[2048 + du];
            float zo  = zf[bq * 32 + 24 + dd] + l0b[3072 + du];
            float ii = sigmoidf_(zi), ff = sigmoidf_(zff), oo = sigmoidf_(zo);
            c0r = ff * c0r + ii * tanhf(zg);
            __stcg(&g_h0[wb][bq * DDIM + du], oo * tanhf(c0r));
        }
        grid_bar();

        // ======== phase B: LSTM1 GEMM + gates ========
        gemm_mma<2560, 1024, 1536, DDIM>(dsm, j, g_h0[wb], g_ctx, g_h1[rb],
                                         g_pb1, zf);
        if (tid < 256) {
            float zi  = zf[bq * 32 + dd]      + l1b[du];
            float zff = zf[bq * 32 + 8 + dd]  + l1b[1024 + du];
            float zg  = zf[bq * 32 + 16 + dd] + l1b[2048 + du];
            float zo  = zf[bq * 32 + 24 + dd] + l1b[3072 + du];
            float ii = sigmoidf_(zi), ff = sigmoidf_(zff), oo = sigmoidf_(zo);
            c1r = ff * c1r + ii * tanhf(zg);
            float h = oo * tanhf(c1r);
            __stcg(&g_h1[wb][bq * DDIM + du], h);
            g_h1all[((size_t)t * BN + bq) * DDIM + du] = h;
        }
        grid_bar();

        // ======== phase C: attention energies (CTA = b x a-chunk) ========
        {
            const float* h1cur = g_h1[wb];
            {   // qp partials: 16 parts x 64 k
                int al = tid & 31, part = tid >> 5;
                float a0 = 0.f;
                int k0 = part * 64;
                #pragma unroll 4
                for (int k = k0; k < k0 + 64; k++)
                    a0 += __ldcg(h1cur + ab * DDIM + k) * qw[k * ADIM + ach * 32 + al];
                sc->qred[part][al] = a0;
            }
            for (int i = tid; i < TIN + KSZ - 1; i += NTHR) {
                int jj = i - (KSZ / 2);
                sc->wp[i] = (jj >= 0 && jj < TIN) ? __ldcg(&g_wcum[ab * TIN + jj]) : 0.f;
            }
            for (int i = tid; i < KSZ * NFLT; i += NTHR) sc->cws[i] = cw[i];
            if (tid < NFLT) sc->cbs[tid] = cb[tid];
            for (int i = tid; i < NFLT * 32; i += NTHR) {
                int f = i >> 5, al = i & 31;
                sc->ldws[i] = ldw[f * ADIM + ach * 32 + al];
            }
            if (tid < 32) {
                sc->ldbs[tid] = ldb[ach * 32 + tid];
                sc->vws[tid]  = vw[ach * 32 + tid];
            }
            __syncthreads();
            if (tid < 32) {
                float s = 0.f;
                #pragma unroll
                for (int p = 0; p < 16; p++) s += sc->qred[p][tid];
                sc->qp[tid] = s + qb[ach * 32 + tid];
            }
            {   // conv staged once: thread (ti, fhalf) does 16 filters
                int ti = tid & 255, fh = tid >> 8;
                float lf[16];
                #pragma unroll
                for (int f = 0; f < 16; f++) lf[f] = sc->cbs[fh * 16 + f];
                for (int jk = 0; jk < KSZ; jk++) {
                    float w = sc->wp[ti + jk];
                    #pragma unroll
                    for (int f = 0; f < 16; f++)
                        lf[f] += w * sc->cws[jk * NFLT + fh * 16 + f];
                }
                #pragma unroll
                for (int f = 0; f < 16; f++) sc->loc[ti][fh * 16 + f] = lf[f];
            }
            __syncthreads();
            {   // energies: thread (ti, a-half)
                int ti = tid & 255, ah = tid >> 8;
                float locv[NFLT];
                #pragma unroll
                for (int f = 0; f < NFLT; f++) locv[f] = sc->loc[ti][f];
                float e = 0.f;
                #pragma unroll 4
                for (int al16 = 0; al16 < 16; al16++) {
                    int al = ah * 16 + al16;
                    int a = ach * 32 + al;
                    float s = sc->qp[al] + g_keysT[(ab * ADIM + a) * TIN + ti] +
                              sc->ldbs[al];
                    #pragma unroll
                    for (int f = 0; f < NFLT; f++) s += locv[f] * sc->ldws[f * 32 + al];
                    e += tanhf(s) * sc->vws[al];
                }
                sc->es[ah][ti] = e;
            }
            __syncthreads();
            if (tid < 256)
                __stcg(&g_epart[(ach * BN + ab) * TIN + tid],
                       sc->es[0][tid] + sc->es[1][tid]);
        }
        grid_bar();

        // ======== phase D: softmax + context (CTA = b x E-chunk) ========
        {
            const int ec = ach;
            float ev = 0.f, ex = 0.f;
            if (tid < 256) {
                ev = vb[0] + g_maskneg[ab * TIN + tid];
                #pragma unroll
                for (int ac = 0; ac < 4; ac++)
                    ev += __ldcg(&g_epart[(ac * BN + ab) * TIN + tid]);
                sd->red[tid] = ev;
            }
            __syncthreads();
            for (int s = 128; s > 0; s >>= 1) {
                if (tid < s) sd->red[tid] = fmaxf(sd->red[tid], sd->red[tid + s]);
                __syncthreads();
            }
            float mx = sd->red[0];
            __syncthreads();
            if (tid < 256) { ex = expf(ev - mx); sd->red[tid] = ex; }
            __syncthreads();
            for (int s = 128; s > 0; s >>= 1) {
                if (tid < s) sd->red[tid] += sd->red[tid + s];
                __syncthreads();
            }
            float inv = 1.f / sd->red[0];
            __syncthreads();
            if (tid < 256) {
                float w = ex * inv;
                sd->ws[tid] = w;
                if (ec == 0) {
                    __stcg(&g_wcum[ab * TIN + tid],
                           __ldcg(&g_wcum[ab * TIN + tid]) + w);
                    out_align[((size_t)ab * TOUT + t) * TIN + tid] = w;
                }
            }
            __syncthreads();
            {   // context: 128 cols x 4 t-quarters
                int cl = tid & 127, q = tid >> 7;
                float acc = 0.f;
                #pragma unroll 4
                for (int tt = q * 64; tt < q * 64 + 64; tt++)
                    acc += sd->ws[tt] *
                           memory[((size_t)ab * TIN + tt) * EDIM + ec * 128 + cl];
                sd->cred[q][cl] = acc;
                __syncthreads();
                if (tid < 128) {
                    float cv = sd->cred[0][tid] + sd->cred[1][tid] +
                               sd->cred[2][tid] + sd->cred[3][tid];
                    __stcg(&g_ctx[ab * EDIM + ec * 128 + tid], cv);
                    g_ctxall[((size_t)t * BN + ab) * EDIM + ec * 128 + tid] = cv;
                }
            }
        }
        grid_bar();
    }
}

// ---------------- prenet (teacher-forced, fully parallel) ----------------
__global__ void prenet_kernel(const float* __restrict__ targets,
                              const float* __restrict__ w1, const float* __restrict__ b1,
                              const float* __restrict__ w2, const float* __restrict__ b2) {
    int bid = blockIdx.x;          // t*BN + b
    int t = bid >> 5, b = bid & 31;
    __shared__ float xin[NMEL];
    __shared__ float h[PRE];
    int tid = threadIdx.x;         // 256
    if (tid < NMEL) xin[tid] = (t == 0) ? 0.f : targets[(b * TOUT + (t - 1)) * NMEL + tid];
    __syncthreads();
    float acc = b1[tid];
    #pragma unroll 8
    for (int k = 0; k < NMEL; k++) acc += xin[k] * w1[k * PRE + tid];
    h[tid] = fmaxf(acc, 0.f);
    __syncthreads();
    float acc2 = b2[tid];
    #pragma unroll 8
    for (int k = 0; k < PRE; k++) acc2 += h[k] * w2[k * PRE + tid];
    g_prenet[(t * BN + b) * PRE + tid] = fmaxf(acc2, 0.f);
}

// ---------------- keys projection, stored transposed [b][a][t] ----------------
__global__ void keys_kernel(const float* __restrict__ memory,
                            const float* __restrict__ mw, const float* __restrict__ mb) {
    int bid = blockIdx.x;          // b*TIN + t
    int b = bid >> 8, t = bid & 255;
    __shared__ float x[EDIM];
    int tid = threadIdx.x;         // 128
    for (int i = tid; i < EDIM; i += 128) x[i] = memory[(b * TIN + t) * EDIM + i];
    __syncthreads();
    float acc = mb[tid];
    #pragma unroll 8
    for (int k = 0; k < EDIM; k++) acc += x[k] * mw[k * ADIM + tid];
    g_keysT[(b * ADIM + tid) * TIN + t] = acc;
}

// ---------------- output projections (post-pass) ----------------
__global__ void proj_kernel(const float* __restrict__ pw, const float* __restrict__ pb,
                            const float* __restrict__ gw, const float* __restrict__ gb,
                            float* __restrict__ out_mel, float* __restrict__ out_gate) {
    int bid = blockIdx.x;          // t*BN + b
    int t = bid >> 5, b = bid & 31;
    __shared__ float xo[DDIM + EDIM];
    int tid = threadIdx.x;         // 128
    for (int i = tid; i < DDIM; i += 128) xo[i] = g_h1all[(size_t)(t * BN + b) * DDIM + i];
    for (int i = tid; i < EDIM; i += 128) xo[DDIM + i] = g_ctxall[(size_t)(t * BN + b) * EDIM + i];
    __syncthreads();
    if (tid < NMEL) {
        float acc = pb[tid];
        #pragma unroll 8
        for (int k = 0; k < DDIM + EDIM; k++) acc += xo[k] * pw[k * NMEL + tid];
        out_mel[(size_t)(b * TOUT + t) * NMEL + tid] = acc;
    } else if (tid == NMEL) {
        float acc = gb[0];
        for (int k = 0; k < DDIM + EDIM; k++) acc += xo[k] * gw[k];
        out_gate[b * TOUT + t] = acc;
    }
}

// ---------------- launcher ----------------
extern "C" void kernel_launch(void* const* d_in, const int* in_sizes, int n_in,
                              void* d_out, int out_size) {
    (void)in_sizes; (void)n_in; (void)out_size;
    const float* memory  = (const float*)d_in[0];
    const float* targets = (const float*)d_in[1];
    const unsigned char* mask = (const unsigned char*)d_in[2];
    const float* p1w = (const float*)d_in[3];
    const float* p1b = (const float*)d_in[4];
    const float* p2w = (const float*)d_in[5];
    const float* p2b = (const float*)d_in[6];
    const float* l0k = (const float*)d_in[7];
    const float* l0r = (const float*)d_in[8];
    const float* l0b = (const float*)d_in[9];
    const float* l1k = (const float*)d_in[10];
    const float* l1r = (const float*)d_in[11];
    const float* l1b = (const float*)d_in[12];
    const float* qw  = (const float*)d_in[13];
    const float* qb  = (const float*)d_in[14];
    const float* mw  = (const float*)d_in[15];
    const float* mb  = (const float*)d_in[16];
    const float* vw  = (const float*)d_in[17];
    const float* vb  = (const float*)d_in[18];
    const float* ccw = (const float*)d_in[19];
    const float* ccb = (const float*)d_in[20];
    const float* ldw = (const float*)d_in[21];
    const float* ldb = (const float*)d_in[22];
    const float* pw  = (const float*)d_in[23];
    const float* pb  = (const float*)d_in[24];
    const float* gw  = (const float*)d_in[25];
    const float* gb  = (const float*)d_in[26];

    float* out       = (float*)d_out;
    float* out_mel   = out;                              // [B, TOUT, NMEL]
    float* out_gate  = out + (size_t)BN * TOUT * NMEL;   // [B, TOUT, 1]
    float* out_align = out_gate + (size_t)BN * TOUT;     // [B, TOUT, TIN]

    static int smem_set = 0;
    if (!smem_set) {
        cudaFuncSetAttribute(decoder_persist,
                             cudaFuncAttributeMaxDynamicSharedMemorySize, DSMEM_BYTES);
        smem_set = 1;
    }

    uint4* pb0;
    uint4* pb1;
    cudaGetSymbolAddress((void**)&pb0, g_pb0);
    cudaGetSymbolAddress((void**)&pb1, g_pb1);

    mask_kernel<<<1, 256>>>(mask);
    pack_kernel<KST0, 768><<<dim3(KST0, 32), 256>>>(l0k, l0r, pb0);
    pack_kernel<KST1, 1536><<<dim3(KST1, 32), 256>>>(l1k, l1r, pb1);
    prenet_kernel<<<TOUT * BN, 256>>>(targets, p1w, p1b, p2w, p2b);
    keys_kernel<<<BN * TIN, 128>>>(memory, mw, mb);
    decoder_persist<<<NCTA, NTHR, DSMEM_BYTES>>>(memory, l0b, l1b, qw, qb, vw, vb,
                                                 ccw, ccb, ldw, ldb, out_align);
    proj_kernel<<<TOUT * BN, 128>>>(pw, pb, gw, gb, out_mel, out_gate);
}

// round 8
// speedup vs baseline: 3.8239x; 1.4328x over previous
#include <cuda_runtime.h>
#include <cuda_bf16.h>
#include <math.h>
#include <string.h>

#define BN 32
#define TIN 256
#define TOUT 400
#define EDIM 512
#define ADIM 128
#define NFLT 32
#define KSZ 31
#define PRE 256
#define DDIM 1024
#define NMEL 80
#define ZN 4096
#define NCTA 128
#define NTHR 512
#define CHUNKK 128
#define KSPC 8                 // ksteps (16k) per chunk
#define KST0 112               // 1792/16
#define KST1 160               // 2560/16
#define DSMEM_BYTES 104448     // 64K Bbuf + 34816 x + 4096 zf

// ---------------- persistent device scratch ----------------
__device__ float g_prenet[TOUT * BN * PRE];   // [t][b][k]
__device__ float g_keysT[BN * ADIM * TIN];    // [b][a][t]
__device__ float g_maskneg[BN * TIN];         // 0 or -1e9
__device__ float g_h0[2][BN * DDIM];
__device__ float g_h1[2][BN * DDIM];
__device__ float g_ctx[BN * EDIM];
__device__ float g_wcum[BN * TIN];
__device__ float g_epart[4 * BN * TIN];       // [achunk][b][ti]
__device__ float g_h1all[TOUT * BN * DDIM];   // [t][b][d]
__device__ float g_ctxall[TOUT * BN * EDIM];  // [t][b][e]
__device__ unsigned g_barc;
__device__ volatile unsigned g_barg;
// packed bf16 hi/lo weights in mma fragment order:
// [j][kstep][g][lane] : uint4 = {bh0, bh1, bl0, bl1}
__device__ uint4 g_pb0[(size_t)NCTA * KST0 * 4 * 32];
__device__ uint4 g_pb1[(size_t)NCTA * KST1 * 4 * 32];

__device__ __forceinline__ float sigmoidf_(float x) { return 1.f / (1.f + expf(-x)); }

__device__ __forceinline__ unsigned smem_u32(const void* p) {
    unsigned a;
    asm("{ .reg .u64 t; cvta.to.shared.u64 t, %1; cvt.u32.u64 %0, t; }"
        : "=r"(a) : "l"(p));
    return a;
}
__device__ __forceinline__ void cpasync16(unsigned dst, const void* src) {
    asm volatile("cp.async.cg.shared.global [%0], [%1], 16;" :: "r"(dst), "l"(src));
}
#define CP_COMMIT() asm volatile("cp.async.commit_group;" ::: "memory")
#define CP_WAITG(n) asm volatile("cp.async.wait_group %0;" :: "n"(n) : "memory")

__device__ __forceinline__ unsigned pk2(__nv_bfloat16 a, __nv_bfloat16 b) {
    __nv_bfloat162 t(a, b);
    unsigned r;
    memcpy(&r, &t, 4);
    return r;
}
__device__ __forceinline__ void mma16816(float& d0, float& d1, float& d2, float& d3,
                                         unsigned a0, unsigned a1, unsigned a2,
                                         unsigned a3, unsigned b0, unsigned b1) {
    asm volatile("mma.sync.aligned.m16n8k16.row.col.f32.bf16.bf16.f32 "
                 "{%0,%1,%2,%3}, {%4,%5,%6,%7}, {%8,%9}, {%0,%1,%2,%3};"
                 : "+f"(d0), "+f"(d1), "+f"(d2), "+f"(d3)
                 : "r"(a0), "r"(a1), "r"(a2), "r"(a3), "r"(b0), "r"(b1));
}

// ---------------- grid barrier ----------------
__device__ __forceinline__ void grid_bar() {
    __syncthreads();
    if (threadIdx.x == 0) {
        __threadfence();
        unsigned gen = g_barg;
        if (atomicInc(&g_barc, NCTA - 1) == NCTA - 1) {
            g_barg = gen + 1;
            __threadfence();
        } else {
            while (g_barg == gen) __nanosleep(32);
        }
        __threadfence();
    }
    __syncthreads();
}

// ---------------- attention smem structs (alias the gemm region) ------------
struct AttC {
    float wp[TIN + KSZ];
    float cws[KSZ * NFLT];
    float cbs[NFLT];
    float ldws[NFLT * 32];
    float ldbs[32], vws[32];
    float qred[16][32];
    float qp[32];
    float es[2][TIN];
    float loc[TIN][NFLT + 1];   // padded: conflict-free column reads
};
struct AttD { float red[256]; float ws[256]; float cred[4][128]; };

// ---------------- mask prologue ----------------
__global__ void mask_kernel(const unsigned char* __restrict__ mask) {
    __shared__ int s_has;
    int tid = threadIdx.x;
    if (tid == 0) s_has = 0;
    __syncthreads();
    int local = 0;
    for (int i = tid; i < BN * TIN; i += 256)
        if ((i & 3) != 0 && mask[i] != 0) local = 1;
    if (local) atomicOr(&s_has, 1);
    __syncthreads();
    bool is_u8 = (s_has != 0);
    const int* mi = (const int*)mask;
    for (int i = tid; i < BN * TIN; i += 256) {
        int v = is_u8 ? (int)mask[i] : mi[i];
        g_maskneg[i] = v ? 0.f : -1e9f;
    }
}

// ---------------- weight pack: fp32 [k][4096] -> fragment-order bf16 hi/lo ---
template <int KST, int KB1>
__global__ void pack_kernel(const float* __restrict__ wK, const float* __restrict__ wR,
                            uint4* __restrict__ out) {
    int ks = blockIdx.x, nb = blockIdx.y;
    __shared__ float w[16][128];
    int k0 = ks * 16;
    const float* W = (k0 < KB1) ? wK + (size_t)k0 * ZN : wR + (size_t)(k0 - KB1) * ZN;
    int N0 = nb * 128;
    for (int i = threadIdx.x; i < 2048; i += 256) {
        int kk = i >> 7, n = i & 127;
        w[kk][n] = W[(size_t)kk * ZN + N0 + n];
    }
    __syncthreads();
    int g = N0 >> 10, jbase = (N0 & 1023) >> 3;
    for (int s = threadIdx.x; s < 512; s += 256) {
        int jl = s >> 5, lane = s & 31;
        int q = lane & 3, t4 = lane >> 2;
        int n = jl * 8 + t4;
        float v0 = w[2 * q][n], v1 = w[2 * q + 1][n];
        float v2 = w[2 * q + 8][n], v3 = w[2 * q + 9][n];
        __nv_bfloat16 h0 = __float2bfloat16_rn(v0), h1 = __float2bfloat16_rn(v1);
        __nv_bfloat16 h2 = __float2bfloat16_rn(v2), h3 = __float2bfloat16_rn(v3);
        unsigned bh0 = pk2(h0, h1), bh1 = pk2(h2, h3);
        unsigned bl0 = pk2(__float2bfloat16_rn(v0 - __bfloat162float(h0)),
                           __float2bfloat16_rn(v1 - __bfloat162float(h1)));
        unsigned bl1 = pk2(__float2bfloat16_rn(v2 - __bfloat162float(h2)),
                           __float2bfloat16_rn(v3 - __bfloat162float(h3)));
        int j = jbase + jl;
        out[((size_t)(j * KST + ks) * 4 + g) * 32 + lane] = make_uint4(bh0, bh1, bl0, bl1);
    }
}

// ---------------- warp-specialized bf16 MMA GEMM --------------------------
// rows = 32 batch; cols = CTA j's 32 units-by-gates {1024g + 8j + i}.
// warps 0..7 consumers (mi = w&1, g = w>>1); warps 8..15 producers.
// zf[row*32 + 8g + i] gets the fully-reduced fp32 result.
template <int KTOT, int KB0, int KB1, int SA>
__device__ __forceinline__ void gemm_mma(char* dsm, int j,
                                         const float* __restrict__ xA,
                                         const float* __restrict__ xB,
                                         const float* __restrict__ xC,
                                         const uint4* __restrict__ pB,
                                         float* __restrict__ zf) {
    constexpr int NC = KTOT / CHUNKK;
    constexpr int KST = KTOT / 16;
    const int tid = threadIdx.x;
    uint4* Bb = (uint4*)dsm;                                   // [4][KSPC][4][32]
    __nv_bfloat16* xh = (__nv_bfloat16*)(dsm + 65536);         // [2][32][136]
    __nv_bfloat16* xl = xh + 2 * 32 * 136;

    if (tid >= 256) {
        // =============== producers ===============
        const int p = tid - 256;
        const int row = p >> 3, kseg = p & 7;
        float4 xr[2][4];
        auto ldgx = [&](int c, int set) {
            int k0 = c * CHUNKK + kseg * 16;
            const float* s;
            if (k0 < KB0)      s = xA + row * SA + k0;
            else if (k0 < KB1) s = xB + row * EDIM + (k0 - KB0);
            else               s = xC + row * DDIM + (k0 - KB1);
            #pragma unroll
            for (int i = 0; i < 4; i++) xr[set][i] = __ldcg((const float4*)s + i);
        };
        auto stsx = [&](int c, int set) {
            int bx = c & 1;
            __nv_bfloat16* dh = xh + bx * 4352 + row * 136 + kseg * 16;
            __nv_bfloat16* dl = xl + bx * 4352 + row * 136 + kseg * 16;
            float f[16];
            #pragma unroll
            for (int i = 0; i < 4; i++) {
                f[4 * i] = xr[set][i].x;     f[4 * i + 1] = xr[set][i].y;
                f[4 * i + 2] = xr[set][i].z; f[4 * i + 3] = xr[set][i].w;
            }
            #pragma unroll
            for (int u = 0; u < 8; u++) {
                float a = f[2 * u], b = f[2 * u + 1];
                __nv_bfloat16 ha = __float2bfloat16_rn(a), hb = __float2bfloat16_rn(b);
                ((unsigned*)dh)[u] = pk2(ha, hb);
                ((unsigned*)dl)[u] =
                    pk2(__float2bfloat16_rn(a - __bfloat162float(ha)),
                        __float2bfloat16_rn(b - __bfloat162float(hb)));
            }
        };
        auto cpB = [&](int c) {
            int buf = c & 3;
            const char* src = (const char*)(pB + (size_t)(j * KST + c * KSPC) * 4 * 32);
            char* dst = (char*)(Bb + (size_t)buf * 1024);
            #pragma unroll
            for (int i = 0; i < 4; i++)
                cpasync16(smem_u32(dst + i * 4096 + p * 16), src + i * 4096 + p * 16);
            CP_COMMIT();
        };

        ldgx(0, 0); ldgx(1, 1);
        cpB(0); cpB(1); cpB(2);
        stsx(0, 0);
        ldgx(2, 0);
        CP_WAITG(2);               // B(0) landed
        __syncthreads();
        for (int c = 0; c < NC; c++) {
            if (c + 1 < NC) stsx(c + 1, (c + 1) & 1);
            if (c + 3 < NC) { ldgx(c + 3, (c + 1) & 1); cpB(c + 3); CP_WAITG(2); }
            else if (c + 2 < NC) CP_WAITG(1);
            else if (c + 1 < NC) CP_WAITG(0);
            __syncthreads();
        }
    } else {
        // =============== consumers ===============
        const int w = tid >> 5, lane = tid & 31;
        const int mi = w & 1, g = w >> 1;
        const int t4 = lane >> 2, q = lane & 3;
        const int r0 = mi * 16 + t4;
        float d0 = 0.f, d1 = 0.f, d2 = 0.f, d3 = 0.f;
        __syncthreads();
        for (int c = 0; c < NC; c++) {
            const uint4* Bw = Bb + (c & 3) * 1024 + g * 32 + lane;
            const __nv_bfloat16* xhb = xh + (c & 1) * 4352;
            const __nv_bfloat16* xlb = xl + (c & 1) * 4352;
            #pragma unroll
            for (int ks = 0; ks < KSPC; ks++) {
                int kb = ks * 16 + 2 * q;
                unsigned a0 = *(const unsigned*)(xhb + r0 * 136 + kb);
                unsigned a1 = *(const unsigned*)(xhb + (r0 + 8) * 136 + kb);
                unsigned a2 = *(const unsigned*)(xhb + r0 * 136 + kb + 8);
                unsigned a3 = *(const unsigned*)(xhb + (r0 + 8) * 136 + kb + 8);
                unsigned l0 = *(const unsigned*)(xlb + r0 * 136 + kb);
                unsigned l1 = *(const unsigned*)(xlb + (r0 + 8) * 136 + kb);
                unsigned l2 = *(const unsigned*)(xlb + r0 * 136 + kb + 8);
                unsigned l3 = *(const unsigned*)(xlb + (r0 + 8) * 136 + kb + 8);
                uint4 B = Bw[ks * 128];
                mma16816(d0, d1, d2, d3, a0, a1, a2, a3, B.x, B.y);   // Ah*Bh
                mma16816(d0, d1, d2, d3, l0, l1, l2, l3, B.x, B.y);   // Al*Bh
                mma16816(d0, d1, d2, d3, a0, a1, a2, a3, B.z, B.w);   // Ah*Bl
            }
            __syncthreads();
        }
        zf[r0 * 32 + g * 8 + 2 * q]           = d0;
        zf[r0 * 32 + g * 8 + 2 * q + 1]       = d1;
        zf[(r0 + 8) * 32 + g * 8 + 2 * q]     = d2;
        zf[(r0 + 8) * 32 + g * 8 + 2 * q + 1] = d3;
    }
    __syncthreads();   // publish zf
}

// ---------------- persistent decoder kernel ----------------
__global__ __launch_bounds__(NTHR, 1) void decoder_persist(
    const float* __restrict__ memory,
    const float* __restrict__ l0b, const float* __restrict__ l1b,
    const float* __restrict__ qw, const float* __restrict__ qb,
    const float* __restrict__ vw, const float* __restrict__ vb,
    const float* __restrict__ cw, const float* __restrict__ cb,
    const float* __restrict__ ldw, const float* __restrict__ ldb,
    float* __restrict__ out_align) {
    extern __shared__ char dsm[];
    float* zf = (float*)(dsm + 100352);
    AttC* sc = (AttC*)dsm;
    AttD* sd = (AttD*)dsm;
    const int j = blockIdx.x;
    const int tid = threadIdx.x;

    {   // init state
        int i = j * NTHR + tid;
        if (i < BN * DDIM) {
            g_h0[0][i] = 0.f; g_h0[1][i] = 0.f;
            g_h1[0][i] = 0.f; g_h1[1][i] = 0.f;
        }
        if (i < BN * EDIM) g_ctx[i] = 0.f;
        if (i < BN * TIN)  g_wcum[i] = 0.f;
    }
    float c0r = 0.f, c1r = 0.f;              // cell state in regs (tid<256)
    const int bq = tid >> 3, dd = tid & 7;   // gate mapping: unit (bq, 8j+dd)
    const int du = 8 * j + dd;
    const int ab = j >> 2, ach = j & 3;      // attention mapping

    grid_bar();

    for (int t = 0; t < TOUT; t++) {
        const int rb = t & 1, wb = (t + 1) & 1;

        // ======== phase A: LSTM0 GEMM + gates ========
        gemm_mma<1792, 256, 768, PRE>(dsm, j, g_prenet + (size_t)t * BN * PRE,
                                      g_ctx, g_h0[rb], g_pb0, zf);
        if (tid < 256) {
            float zi  = zf[bq * 32 + dd]      + l0b[du];
            float zff = zf[bq * 32 + 8 + dd]  + l0b[1024 + du];
            float zg  = zf[bq * 32 + 16 + dd] + l0b[2048 + du];
            float zo  = zf[bq * 32 + 24 + dd] + l0b[3072 + du];
            float ii = sigmoidf_(zi), ff = sigmoidf_(zff), oo = sigmoidf_(zo);
            c0r = ff * c0r + ii * tanhf(zg);
            __stcg(&g_h0[wb][bq * DDIM + du], oo * tanhf(c0r));
        }
        grid_bar();

        // ======== phase B: LSTM1 GEMM + gates ========
        gemm_mma<2560, 1024, 1536, DDIM>(dsm, j, g_h0[wb], g_ctx, g_h1[rb],
                                         g_pb1, zf);
        if (tid < 256) {
            float zi  = zf[bq * 32 + dd]      + l1b[du];
            float zff = zf[bq * 32 + 8 + dd]  + l1b[1024 + du];
            float zg  = zf[bq * 32 + 16 + dd] + l1b[2048 + du];
            float zo  = zf[bq * 32 + 24 + dd] + l1b[3072 + du];
            float ii = sigmoidf_(zi), ff = sigmoidf_(zff), oo = sigmoidf_(zo);
            c1r = ff * c1r + ii * tanhf(zg);
            float h = oo * tanhf(c1r);
            __stcg(&g_h1[wb][bq * DDIM + du], h);
            g_h1all[((size_t)t * BN + bq) * DDIM + du] = h;
        }
        grid_bar();

        // ======== phase C: attention energies (CTA = b x a-chunk) ========
        {
            const float* h1cur = g_h1[wb];
            {   // qp partials: 16 parts x 64 k
                int al = tid & 31, part = tid >> 5;
                float a0 = 0.f;
                int k0 = part * 64;
                #pragma unroll 4
                for (int k = k0; k < k0 + 64; k++)
                    a0 += __ldcg(h1cur + ab * DDIM + k) * qw[k * ADIM + ach * 32 + al];
                sc->qred[part][al] = a0;
            }
            for (int i = tid; i < TIN + KSZ - 1; i += NTHR) {
                int jj = i - (KSZ / 2);
                sc->wp[i] = (jj >= 0 && jj < TIN) ? __ldcg(&g_wcum[ab * TIN + jj]) : 0.f;
            }
            for (int i = tid; i < KSZ * NFLT; i += NTHR) sc->cws[i] = cw[i];
            if (tid < NFLT) sc->cbs[tid] = cb[tid];
            for (int i = tid; i < NFLT * 32; i += NTHR) {
                int f = i >> 5, al = i & 31;
                sc->ldws[i] = ldw[f * ADIM + ach * 32 + al];
            }
            if (tid < 32) {
                sc->ldbs[tid] = ldb[ach * 32 + tid];
                sc->vws[tid]  = vw[ach * 32 + tid];
            }
            __syncthreads();
            if (tid < 32) {
                float s = 0.f;
                #pragma unroll
                for (int p = 0; p < 16; p++) s += sc->qred[p][tid];
                sc->qp[tid] = s + qb[ach * 32 + tid];
            }
            {   // conv staged once: thread (ti, fhalf) does 16 filters
                int ti = tid & 255, fh = tid >> 8;
                float lf[16];
                #pragma unroll
                for (int f = 0; f < 16; f++) lf[f] = sc->cbs[fh * 16 + f];
                for (int jk = 0; jk < KSZ; jk++) {
                    float w = sc->wp[ti + jk];
                    #pragma unroll
                    for (int f = 0; f < 16; f++)
                        lf[f] += w * sc->cws[jk * NFLT + fh * 16 + f];
                }
                #pragma unroll
                for (int f = 0; f < 16; f++) sc->loc[ti][fh * 16 + f] = lf[f];
            }
            __syncthreads();
            {   // energies: thread (ti, a-half)
                int ti = tid & 255, ah = tid >> 8;
                float locv[NFLT];
                #pragma unroll
                for (int f = 0; f < NFLT; f++) locv[f] = sc->loc[ti][f];
                float e = 0.f;
                #pragma unroll 4
                for (int al16 = 0; al16 < 16; al16++) {
                    int al = ah * 16 + al16;
                    int a = ach * 32 + al;
                    float s = sc->qp[al] + g_keysT[(ab * ADIM + a) * TIN + ti] +
                              sc->ldbs[al];
                    #pragma unroll
                    for (int f = 0; f < NFLT; f++) s += locv[f] * sc->ldws[f * 32 + al];
                    e += tanhf(s) * sc->vws[al];
                }
                sc->es[ah][ti] = e;
            }
            __syncthreads();
            if (tid < 256)
                __stcg(&g_epart[(ach * BN + ab) * TIN + tid],
                       sc->es[0][tid] + sc->es[1][tid]);
        }
        grid_bar();

        // ======== phase D: softmax + context (CTA = b x E-chunk) ========
        {
            const int ec = ach;
            float ev = 0.f, ex = 0.f;
            if (tid < 256) {
                ev = vb[0] + g_maskneg[ab * TIN + tid];
                #pragma unroll
                for (int ac = 0; ac < 4; ac++)
                    ev += __ldcg(&g_epart[(ac * BN + ab) * TIN + tid]);
                sd->red[tid] = ev;
            }
            __syncthreads();
            for (int s = 128; s > 0; s >>= 1) {
                if (tid < s) sd->red[tid] = fmaxf(sd->red[tid], sd->red[tid + s]);
                __syncthreads();
            }
            float mx = sd->red[0];
            __syncthreads();
            if (tid < 256) { ex = expf(ev - mx); sd->red[tid] = ex; }
            __syncthreads();
            for (int s = 128; s > 0; s >>= 1) {
                if (tid < s) sd->red[tid] += sd->red[tid + s];
                __syncthreads();
            }
            float inv = 1.f / sd->red[0];
            __syncthreads();
            if (tid < 256) {
                float w = ex * inv;
                sd->ws[tid] = w;
                if (ec == 0) {
                    __stcg(&g_wcum[ab * TIN + tid],
                           __ldcg(&g_wcum[ab * TIN + tid]) + w);
                    out_align[((size_t)ab * TOUT + t) * TIN + tid] = w;
                }
            }
            __syncthreads();
            {   // context: 128 cols x 4 t-quarters
                int cl = tid & 127, q = tid >> 7;
                float acc = 0.f;
                #pragma unroll 4
                for (int tt = q * 64; tt < q * 64 + 64; tt++)
                    acc += sd->ws[tt] *
                           memory[((size_t)ab * TIN + tt) * EDIM + ec * 128 + cl];
                sd->cred[q][cl] = acc;
                __syncthreads();
                if (tid < 128) {
                    float cv = sd->cred[0][tid] + sd->cred[1][tid] +
                               sd->cred[2][tid] + sd->cred[3][tid];
                    __stcg(&g_ctx[ab * EDIM + ec * 128 + tid], cv);
                    g_ctxall[((size_t)t * BN + ab) * EDIM + ec * 128 + tid] = cv;
                }
            }
        }
        grid_bar();
    }
}

// ---------------- prenet (teacher-forced, fully parallel) ----------------
__global__ void prenet_kernel(const float* __restrict__ targets,
                              const float* __restrict__ w1, const float* __restrict__ b1,
                              const float* __restrict__ w2, const float* __restrict__ b2) {
    int bid = blockIdx.x;          // t*BN + b
    int t = bid >> 5, b = bid & 31;
    __shared__ float xin[NMEL];
    __shared__ float h[PRE];
    int tid = threadIdx.x;         // 256
    if (tid < NMEL) xin[tid] = (t == 0) ? 0.f : targets[(b * TOUT + (t - 1)) * NMEL + tid];
    __syncthreads();
    float acc = b1[tid];
    #pragma unroll 8
    for (int k = 0; k < NMEL; k++) acc += xin[k] * w1[k * PRE + tid];
    h[tid] = fmaxf(acc, 0.f);
    __syncthreads();
    float acc2 = b2[tid];
    #pragma unroll 8
    for (int k = 0; k < PRE; k++) acc2 += h[k] * w2[k * PRE + tid];
    g_prenet[(t * BN + b) * PRE + tid] = fmaxf(acc2, 0.f);
}

// ---------------- keys projection, stored transposed [b][a][t] ----------------
__global__ void keys_kernel(const float* __restrict__ memory,
                            const float* __restrict__ mw, const float* __restrict__ mb) {
    int bid = blockIdx.x;          // b*TIN + t
    int b = bid >> 8, t = bid & 255;
    __shared__ float x[EDIM];
    int tid = threadIdx.x;         // 128
    for (int i = tid; i < EDIM; i += 128) x[i] = memory[(b * TIN + t) * EDIM + i];
    __syncthreads();
    float acc = mb[tid];
    #pragma unroll 8
    for (int k = 0; k < EDIM; k++) acc += x[k] * mw[k * ADIM + tid];
    g_keysT[(b * ADIM + tid) * TIN + t] = acc;
}

// ---------------- output projections (post-pass) ----------------
__global__ void proj_kernel(const float* __restrict__ pw, const float* __restrict__ pb,
                            const float* __restrict__ gw, const float* __restrict__ gb,
                            float* __restrict__ out_mel, float* __restrict__ out_gate) {
    int bid = blockIdx.x;          // t*BN + b
    int t = bid >> 5, b = bid & 31;
    __shared__ float xo[DDIM + EDIM];
    int tid = threadIdx.x;         // 128
    for (int i = tid; i < DDIM; i += 128) xo[i] = g_h1all[(size_t)(t * BN + b) * DDIM + i];
    for (int i = tid; i < EDIM; i += 128) xo[DDIM + i] = g_ctxall[(size_t)(t * BN + b) * EDIM + i];
    __syncthreads();
    if (tid < NMEL) {
        float acc = pb[tid];
        #pragma unroll 8
        for (int k = 0; k < DDIM + EDIM; k++) acc += xo[k] * pw[k * NMEL + tid];
        out_mel[(size_t)(b * TOUT + t) * NMEL + tid] = acc;
    } else if (tid == NMEL) {
        float acc = gb[0];
        for (int k = 0; k < DDIM + EDIM; k++) acc += xo[k] * gw[k];
        out_gate[b * TOUT + t] = acc;
    }
}

// ---------------- launcher ----------------
extern "C" void kernel_launch(void* const* d_in, const int* in_sizes, int n_in,
                              void* d_out, int out_size) {
    (void)in_sizes; (void)n_in; (void)out_size;
    const float* memory  = (const float*)d_in[0];
    const float* targets = (const float*)d_in[1];
    const unsigned char* mask = (const unsigned char*)d_in[2];
    const float* p1w = (const float*)d_in[3];
    const float* p1b = (const float*)d_in[4];
    const float* p2w = (const float*)d_in[5];
    const float* p2b = (const float*)d_in[6];
    const float* l0k = (const float*)d_in[7];
    const float* l0r = (const float*)d_in[8];
    const float* l0b = (const float*)d_in[9];
    const float* l1k = (const float*)d_in[10];
    const float* l1r = (const float*)d_in[11];
    const float* l1b = (const float*)d_in[12];
    const float* qw  = (const float*)d_in[13];
    const float* qb  = (const float*)d_in[14];
    const float* mw  = (const float*)d_in[15];
    const float* mb  = (const float*)d_in[16];
    const float* vw  = (const float*)d_in[17];
    const float* vb  = (const float*)d_in[18];
    const float* ccw = (const float*)d_in[19];
    const float* ccb = (const float*)d_in[20];
    const float* ldw = (const float*)d_in[21];
    const float* ldb = (const float*)d_in[22];
    const float* pw  = (const float*)d_in[23];
    const float* pb  = (const float*)d_in[24];
    const float* gw  = (const float*)d_in[25];
    const float* gb  = (const float*)d_in[26];

    float* out       = (float*)d_out;
    float* out_mel   = out;                              // [B, TOUT, NMEL]
    float* out_gate  = out + (size_t)BN * TOUT * NMEL;   // [B, TOUT, 1]
    float* out_align = out_gate + (size_t)BN * TOUT;     // [B, TOUT, TIN]

    static int smem_set = 0;
    if (!smem_set) {
        cudaFuncSetAttribute(decoder_persist,
                             cudaFuncAttributeMaxDynamicSharedMemorySize, DSMEM_BYTES);
        smem_set = 1;
    }

    uint4* pb0;
    uint4* pb1;
    cudaGetSymbolAddress((void**)&pb0, g_pb0);
    cudaGetSymbolAddress((void**)&pb1, g_pb1);

    mask_kernel<<<1, 256>>>(mask);
    pack_kernel<KST0, 768><<<dim3(KST0, 32), 256>>>(l0k, l0r, pb0);
    pack_kernel<KST1, 1536><<<dim3(KST1, 32), 256>>>(l1k, l1r, pb1);
    prenet_kernel<<<TOUT * BN, 256>>>(targets, p1w, p1b, p2w, p2b);
    keys_kernel<<<BN * TIN, 128>>>(memory, mw, mb);
    decoder_persist<<<NCTA, NTHR, DSMEM_BYTES>>>(memory, l0b, l1b, qw, qb, vw, vb,
                                                 ccw, ccb, ldw, ldb, out_align);
    proj_kernel<<<TOUT * BN, 128>>>(pw, pb, gw, gb, out_mel, out_gate);
}